// round 13
// baseline (speedup 1.0000x reference)
#include <cuda_runtime.h>
#include <cuda_bf16.h>
#include <math.h>

// ---------------- constants ----------------
#define BB   32
#define LL   1024
#define DD   512
#define NH   8
#define HE   64
#define DFF  2048
#define CIN  7
#define MK   4
#define MROWS (BB*LL)          // 32768
#define BLD  (BB*LL*DD)        // 16777216
#define BL7  (BB*LL*CIN)       // 229376
#define TOPK 6

typedef __nv_bfloat16 bf16;

// ---------------- device scratch ----------------
__device__ float g_A   [BLD];
__device__ float g_Bf  [BLD];
__device__ float g_v   [BLD];
__device__ float g_enc [BLD];
__device__ float g_t123[BLD];
__device__ float g_qt  [BLD];
__device__ float g_kt  [BLD];
__device__ float2 g_Sp [BB*NH*4*LL];
__device__ float2 g_sps[BB*LL];
__device__ float g_cm  [BB*DD];
__device__ float g_w   [BB*8];
__device__ int   g_dly [BB*8];
__device__ float g_sx  [BL7];
__device__ float g_tx  [BL7];
__device__ float g_seas[BL7];
__device__ float g_trd [BL7];
__device__ float g_menc[BB*CIN];
// fused V weights (4 attentions)
__device__ float g_wvo4[4*DD*DD];     // Wv @ Wo
__device__ float g_bvo4[4*DD];        // bv@Wo + bo
__device__ float g_wt2 [3*DD*CIN];    // trend conv weights transposed [c][j][d]
__device__ float g_pw2 [CIN*DD];      // proj weights transposed [c][d]
// bf16 split buffers
__device__ bf16 g_mh [12*DD*DD];      // splits: Wq^T[0..3], Wk^T[4..7], WVO^T[8..11]
__device__ bf16 g_ml [12*DD*DD];
__device__ bf16 g_f1h[3*DD*DFF];
__device__ bf16 g_f1l[3*DD*DFF];
__device__ bf16 g_f2h[3*DFF*DD];
__device__ bf16 g_f2l[3*DFF*DD];
__device__ bf16 g_s1h[MROWS*DD];
__device__ bf16 g_s1l[MROWS*DD];
__device__ bf16 g_ench[MROWS*DD];
__device__ bf16 g_encl[MROWS*DD];
__device__ bf16 g_s2h[MROWS*DFF];
__device__ bf16 g_s2l[MROWS*DFF];

struct P4 { const float* p[4]; };
struct P3 { const float* p[3]; };

// ---------------- helpers ----------------
__device__ __forceinline__ void bsplit(float x, bf16& h, bf16& l){
    h = __float2bfloat16(x);
    l = __float2bfloat16(x - __bfloat162float(h));
}
__device__ __forceinline__ unsigned su32(const void* p){
    return (unsigned)__cvta_generic_to_shared(p);
}
__device__ __forceinline__ void cpa16(unsigned dst, const void* src){
    asm volatile("cp.async.cg.shared.global [%0], [%1], 16;" :: "r"(dst), "l"(src));
}
__device__ __forceinline__ void cpa_commit(){
    asm volatile("cp.async.commit_group;" ::: "memory");
}
__device__ __forceinline__ void cpa_wait2(){
    asm volatile("cp.async.wait_group 2;" ::: "memory");
}
__device__ __forceinline__ void ldsm4(unsigned* r, unsigned addr){
    asm volatile("ldmatrix.sync.aligned.m8n8.x4.shared.b16 {%0,%1,%2,%3}, [%4];"
        : "=r"(r[0]), "=r"(r[1]), "=r"(r[2]), "=r"(r[3]) : "r"(addr));
}
__device__ __forceinline__ void mma16(float* d, const unsigned* a, unsigned b0, unsigned b1){
    asm volatile("mma.sync.aligned.m16n8k16.row.col.f32.bf16.bf16.f32 "
        "{%0,%1,%2,%3},{%4,%5,%6,%7},{%8,%9},{%0,%1,%2,%3};"
        : "+f"(d[0]), "+f"(d[1]), "+f"(d[2]), "+f"(d[3])
        : "r"(a[0]), "r"(a[1]), "r"(a[2]), "r"(a[3]), "r"(b0), "r"(b1));
}

// ---------------- split-bf16 mma.sync GEMM ----------------
#define RSTRIDE 80
#define AREA    10240
#define STAGEB  40960
#define GEMM_SMEM (3*STAGEB)
__global__ void __launch_bounds__(512,1) gemm_mma_k(
    const bf16* __restrict__ Ahp, const bf16* __restrict__ Alp,
    const bf16* __restrict__ Bhp, const bf16* __restrict__ Blp,
    const float* __restrict__ bias, const float* __restrict__ res,
    float* __restrict__ C, bf16* __restrict__ Ch, bf16* __restrict__ Cl,
    float* __restrict__ Ct,
    int N, int K, int dogelu)
{
    extern __shared__ __align__(16) char dsm[];
    const int tid = threadIdx.x;
    const int lane = tid & 31, warp = tid >> 5;
    const int wm = warp >> 2, wn = warp & 3;
    const int bx = blockIdx.x, by = blockIdx.y;
    const int S = K >> 5;
    const unsigned sbase = su32(dsm);

    const int lrow = tid >> 2, lc16 = tid & 3;
    const bf16* gA_h = Ahp + (size_t)(by*128 + lrow)*K;
    const bf16* gA_l = Alp + (size_t)(by*128 + lrow)*K;
    const bf16* gB_h = Bhp + (size_t)(bx*128 + lrow)*K;
    const bf16* gB_l = Blp + (size_t)(bx*128 + lrow)*K;
    const unsigned sdst = lrow*RSTRIDE + lc16*16;

    float acc[2][4][4];
#pragma unroll
    for (int i=0;i<2;i++)
#pragma unroll
        for (int j=0;j<4;j++)
#pragma unroll
            for (int t=0;t<4;t++) acc[i][j][t]=0.f;

#pragma unroll
    for (int p=0;p<3;p++){
        if (p < S){
            unsigned b = sbase + p*STAGEB + sdst;
            int gk = p*32 + lc16*8;
            cpa16(b,            gA_h + gk);
            cpa16(b + AREA,     gA_l + gk);
            cpa16(b + 2*AREA,   gB_h + gk);
            cpa16(b + 3*AREA,   gB_l + gk);
        }
        cpa_commit();
    }

    const unsigned arow = (wm*32 + (lane & 15))*RSTRIDE + (lane >> 4)*16;
    const unsigned brow = (wn*32 + (lane & 15))*RSTRIDE + (lane >> 4)*16;

    for (int s=0; s<S; s++){
        cpa_wait2();
        __syncthreads();
        const unsigned sb = sbase + (s % 3)*STAGEB;
#pragma unroll
        for (int k16=0; k16<2; k16++){
            const unsigned ko = k16*32;
            unsigned ah[8], al[8], bh[8], bl[8];
            ldsm4(ah,   sb + arow + ko);
            ldsm4(ah+4, sb + arow + ko + 16*RSTRIDE);
            ldsm4(al,   sb + AREA + arow + ko);
            ldsm4(al+4, sb + AREA + arow + ko + 16*RSTRIDE);
            ldsm4(bh,   sb + 2*AREA + brow + ko);
            ldsm4(bh+4, sb + 2*AREA + brow + ko + 16*RSTRIDE);
            ldsm4(bl,   sb + 3*AREA + brow + ko);
            ldsm4(bl+4, sb + 3*AREA + brow + ko + 16*RSTRIDE);
#pragma unroll
            for (int mf=0; mf<2; mf++){
#pragma unroll
                for (int nf=0; nf<4; nf++){
                    int g = (nf>>1)*4 + (nf&1);
                    mma16(acc[mf][nf], ah+mf*4, bh[g], bh[g+2]);
                    mma16(acc[mf][nf], ah+mf*4, bl[g], bl[g+2]);
                    mma16(acc[mf][nf], al+mf*4, bh[g], bh[g+2]);
                }
            }
        }
        __syncthreads();
        if (s+3 < S){
            unsigned b = sbase + (s % 3)*STAGEB + sdst;
            int gk = (s+3)*32 + lc16*8;
            cpa16(b,            gA_h + gk);
            cpa16(b + AREA,     gA_l + gk);
            cpa16(b + 2*AREA,   gB_h + gk);
            cpa16(b + 3*AREA,   gB_l + gk);
        }
        cpa_commit();
    }

    if (Ct){
        float* st = (float*)dsm;  // [128 cols][129]
#pragma unroll
        for (int mf=0; mf<2; mf++){
#pragma unroll
            for (int nf=0; nf<4; nf++){
                int rl = wm*32 + mf*16 + (lane>>2);
                int cl = wn*32 + nf*8 + ((lane&3)<<1);
                float* d = acc[mf][nf];
#pragma unroll
                for (int h=0; h<2; h++){
                    float b0 = bias ? __ldg(&bias[bx*128 + cl])   : 0.f;
                    float b1 = bias ? __ldg(&bias[bx*128 + cl+1]) : 0.f;
                    st[cl*129 + rl + 8*h]     = d[2*h]   + b0;
                    st[(cl+1)*129 + rl + 8*h] = d[2*h+1] + b1;
                }
            }
        }
        __syncthreads();
        int gr = by*128;
        int b  = gr >> 10;
        int l0 = gr & 1023;
#pragma unroll
        for (int cc=0; cc<8; cc++){
            int col = warp*8 + cc;
            size_t rowoff = ((size_t)b*DD + bx*128 + col)*LL + l0;
#pragma unroll
            for (int i=0;i<4;i++){
                int r = lane + i*32;
                Ct[rowoff + r] = st[col*129 + r];
            }
        }
        return;
    }

#pragma unroll
    for (int mf=0; mf<2; mf++){
#pragma unroll
        for (int nf=0; nf<4; nf++){
            int r0  = by*128 + wm*32 + mf*16 + (lane>>2);
            int col = bx*128 + wn*32 + nf*8 + ((lane&3)<<1);
            float* d = acc[mf][nf];
#pragma unroll
            for (int h=0; h<2; h++){
                int r = r0 + h*8;
                size_t rowoff = (size_t)r * N;
                float2 o = make_float2(d[2*h], d[2*h+1]);
                if (bias){ o.x += __ldg(&bias[col]); o.y += __ldg(&bias[col+1]); }
                if (dogelu){
                    o.x = 0.5f*o.x*(1.0f+erff(o.x*0.7071067811865476f));
                    o.y = 0.5f*o.y*(1.0f+erff(o.y*0.7071067811865476f));
                }
                if (res){
                    float2 rr = *(const float2*)&res[rowoff + col];
                    o.x += rr.x; o.y += rr.y;
                }
                if (Ch){
                    bf16 h0,l0,h1,l1;
                    bsplit(o.x,h0,l0); bsplit(o.y,h1,l1);
                    __nv_bfloat162 hv; hv.x=h0; hv.y=h1;
                    __nv_bfloat162 lv; lv.x=l0; lv.y=l1;
                    *(__nv_bfloat162*)&Ch[rowoff + col] = hv;
                    *(__nv_bfloat162*)&Cl[rowoff + col] = lv;
                } else {
                    *(float2*)&C[rowoff + col] = o;
                }
            }
        }
    }
}

// ---------------- batched 512x512 matmuls: WVO[z] = Wv @ Wo ----------------
__global__ void mmvo_b_k(P4 wb, float* __restrict__ wvo){
    __shared__ float As[32][33], Bs[32][33];
    int z = blockIdx.z;
    const float* A = wb.p[z] + (size_t)2*DD*DD;
    const float* B = wb.p[z] + (size_t)3*DD*DD;
    float* C = wvo + (size_t)z*DD*DD;
    int i0 = blockIdx.y*32, j0 = blockIdx.x*32;
    int tx = threadIdx.x, ty = threadIdx.y;
    float acc[4] = {0.f,0.f,0.f,0.f};
    for (int k0=0;k0<512;k0+=32){
        for (int r=ty;r<32;r+=8){
            As[r][tx] = A[(size_t)(i0+r)*512 + k0+tx];
            Bs[r][tx] = B[(size_t)(k0+r)*512 + j0+tx];
        }
        __syncthreads();
#pragma unroll
        for (int k=0;k<32;k++){
            float bv = Bs[k][tx];
#pragma unroll
            for (int u=0;u<4;u++) acc[u] += As[ty+8*u][k]*bv;
        }
        __syncthreads();
    }
#pragma unroll
    for (int u=0;u<4;u++) C[(size_t)(i0+ty+8*u)*512 + j0+tx] = acc[u];
}

// ---------------- batched fused bias: bvo[z] = bv@Wo + bo ----------------
__global__ void biasvo_b_k(P4 bb, P4 wb, float* __restrict__ bvo){
    int z = blockIdx.y;
    int j = blockIdx.x*256 + threadIdx.x;
    if (j >= 512) return;
    const float* bv = bb.p[z] + 2*DD;
    const float* bo = bb.p[z] + 3*DD;
    const float* Wo = wb.p[z] + (size_t)3*DD*DD;
    float s = bo[j];
    for (int m=0;m<512;m++) s += bv[m]*Wo[(size_t)m*512 + j];
    bvo[z*DD + j] = s;
}

// ---------------- batched split+transpose of 12 512x512 mats ----------------
__global__ void split512b_k(P4 wb, const float* __restrict__ wvo,
                            bf16* __restrict__ oh, bf16* __restrict__ ol){
    __shared__ float t[32][33];
    int z = blockIdx.z;
    const float* W;
    if (z < 4)       W = wb.p[z];
    else if (z < 8)  W = wb.p[z-4] + (size_t)DD*DD;
    else             W = wvo + (size_t)(z-8)*DD*DD;
    bf16* ohp = oh + (size_t)z*DD*DD;
    bf16* olp = ol + (size_t)z*DD*DD;
    int n0 = blockIdx.x*32, k0 = blockIdx.y*32;
    int x = threadIdx.x, y = threadIdx.y;
    for (int i=y;i<32;i+=8)
        t[i][x] = W[(size_t)(k0+i)*DD + n0 + x];
    __syncthreads();
    for (int i=y;i<32;i+=8){
        float v = t[x][i];
        bf16 h,l; bsplit(v,h,l);
        ohp[(size_t)(n0+i)*DD + k0 + x] = h;
        olp[(size_t)(n0+i)*DD + k0 + x] = l;
    }
}

// ---------------- batched split+transpose for FF weights ----------------
__global__ void splitffb_k(P3 Wl, bf16* __restrict__ oh, bf16* __restrict__ ol,
                           int Kd, int Nd){
    __shared__ float t[32][33];
    int z = blockIdx.z;
    const float* W = Wl.p[z];
    bf16* ohp = oh + (size_t)z*Kd*Nd;
    bf16* olp = ol + (size_t)z*Kd*Nd;
    int n0 = blockIdx.x*32, k0 = blockIdx.y*32;
    int x = threadIdx.x, y = threadIdx.y;
    for (int i=y;i<32;i+=8)
        t[i][x] = W[(size_t)(k0+i)*Nd + n0 + x];
    __syncthreads();
    for (int i=y;i<32;i+=8){
        float v = t[x][i];
        bf16 h,l; bsplit(v,h,l);
        ohp[(size_t)(n0+i)*Kd + k0 + x] = h;
        olp[(size_t)(n0+i)*Kd + k0 + x] = l;
    }
}

// ---------------- weight transposes for trendconv/final ----------------
__global__ void wtr_k(const float* __restrict__ Wt, float* __restrict__ Wt2,
                      const float* __restrict__ projW, float* __restrict__ pw2){
    int i = blockIdx.x*256 + threadIdx.x;
    if (i < 3*DD*CIN){
        // Wt2[(c*3 + j)*512 + d] = Wt[(j*512 + d)*7 + c]
        int d = i & 511; int j = (i >> 9) % 3; int c = i / (512*3);
        Wt2[i] = Wt[((size_t)(j*512 + d))*CIN + c];
    }
    int i2 = i - 3*DD*CIN;
    if (i2 >= 0 && i2 < CIN*DD){
        int d = i2 & 511; int c = i2 >> 9;
        pw2[i2] = projW[(size_t)d*CIN + c];
    }
}

// ---------------- FFT helpers ----------------
__device__ __forceinline__ float2 cmul(float2 a, float2 b){
    return make_float2(a.x*b.x - a.y*b.y, a.x*b.y + a.y*b.x);
}
__device__ __forceinline__ int dig4rev(int t){
    int br = __brev(t) >> 22;
    return ((br >> 1) & 0x155) | ((br << 1) & 0x2AA);
}
__device__ void fft1024_r4(float2* z, const float2* tw, int tid, int inv){
    const float s4 = inv ? 1.0f : -1.0f;
#pragma unroll
    for (int s=0; s<5; s++){
        __syncthreads();
        const int quarter = 1 << (2*s);
        const int pos = tid & (quarter-1);
        const int g   = tid >> (2*s);
        const int base = (g << (2*s+2)) + pos;
        const int tstep = pos << (8 - 2*s);
        float2 x0 = z[base];
        float2 x1 = cmul(tw[tstep],   z[base + quarter]);
        float2 x2 = cmul(tw[2*tstep], z[base + 2*quarter]);
        float2 x3 = cmul(tw[3*tstep], z[base + 3*quarter]);
        float2 t0 = make_float2(x0.x+x2.x, x0.y+x2.y);
        float2 t1 = make_float2(x0.x-x2.x, x0.y-x2.y);
        float2 t2 = make_float2(x1.x+x3.x, x1.y+x3.y);
        float2 t3 = make_float2(x1.x-x3.x, x1.y-x3.y);
        float2 rot = make_float2(-s4*t3.y, s4*t3.x);
        z[base]             = make_float2(t0.x+t2.x, t0.y+t2.y);
        z[base+quarter]     = make_float2(t1.x+rot.x, t1.y+rot.y);
        z[base+2*quarter]   = make_float2(t0.x-t2.x, t0.y-t2.y);
        z[base+3*quarter]   = make_float2(t1.x-rot.x, t1.y-rot.y);
    }
    __syncthreads();
}

#define EPB 16
__global__ void corr_fwd_k(const float* __restrict__ qt, const float* __restrict__ kt,
                           float2* __restrict__ Sp){
    __shared__ float2 z[1024];
    __shared__ float2 acc[1024];
    __shared__ float2 tw[1024];
    int bh = blockIdx.x;
    int chunk = blockIdx.y;
    int tid = threadIdx.x;
    for (int j=tid;j<1024;j+=256){
        float s,c; sincosf((float)j * (6.283185307179586f/1024.0f), &s, &c);
        tw[j] = make_float2(c, -s);
    }
    for (int f=tid;f<1024;f+=256) acc[f] = make_float2(0.f,0.f);
    for (int ei=0; ei<EPB; ei++){
        int e = chunk*EPB + ei;
        const float* qp = qt + ((size_t)bh*HE + e)*LL;
        const float* kp = kt + ((size_t)bh*HE + e)*LL;
        __syncthreads();
        for (int t=tid;t<1024;t+=256){
            z[dig4rev(t)] = make_float2(qp[t], kp[t]);
        }
        fft1024_r4(z, tw, tid, 0);
        for (int f=tid;f<1024;f+=256){
            float2 Zf = z[f];
            float2 Zm = z[(1024 - f) & 1023];
            float2 Zc = make_float2(Zm.x, -Zm.y);
            float2 Q  = make_float2(0.5f*(Zf.x+Zc.x), 0.5f*(Zf.y+Zc.y));
            float dx = Zf.x - Zc.x, dy = Zf.y - Zc.y;
            float2 Kk = make_float2(0.5f*dy, -0.5f*dx);
            acc[f].x += Q.x*Kk.x + Q.y*Kk.y;
            acc[f].y += Q.y*Kk.x - Q.x*Kk.y;
        }
    }
    __syncthreads();
    float2* dst = Sp + ((size_t)bh*4 + chunk)*LL;
    for (int f=tid;f<1024;f+=256) dst[f] = acc[f];
}

// ---------------- sum the 32 partial spectra per batch ----------------
__global__ void sumsp_k(const float2* __restrict__ Sp, float2* __restrict__ Sps){
    int b = blockIdx.y;
    int f = blockIdx.x*128 + threadIdx.x;
    float sx=0.f, sy=0.f;
    const float2* sp = Sp + (size_t)b*32*LL + f;
#pragma unroll
    for (int sl=0;sl<32;sl++){
        float2 v = sp[(size_t)sl*LL];
        sx += v.x; sy += v.y;
    }
    Sps[(size_t)b*LL + f] = make_float2(sx, sy);
}

__global__ void corr_topk_k(const float2* __restrict__ Sps, float* __restrict__ wout,
                            int* __restrict__ dout){
    __shared__ float2 z[1024];
    __shared__ float2 tw[1024];
    __shared__ float corr[1024];
    __shared__ float rv[256];
    __shared__ int   ri[256];
    __shared__ float wv[TOPK];
    __shared__ int   dv[TOPK];
    int b = blockIdx.x, tid = threadIdx.x;
    for (int j=tid;j<1024;j+=256){
        float s,c; sincosf((float)j * (6.283185307179586f/1024.0f), &s, &c);
        tw[j] = make_float2(c, s);
    }
    for (int f=tid;f<1024;f+=256){
        z[dig4rev(f)] = Sps[(size_t)b*LL + f];
    }
    fft1024_r4(z, tw, tid, 1);
    const float scale = 1.0f / (1024.0f * 512.0f);
    for (int f=tid;f<1024;f+=256) corr[f] = z[f].x * scale;
    __syncthreads();
    for (int it=0; it<TOPK; it++){
        float best = -1e30f; int bi = 1<<30;
        for (int f=tid;f<1024;f+=256){
            float v = corr[f];
            if (v > best || (v == best && f < bi)){ best = v; bi = f; }
        }
        rv[tid]=best; ri[tid]=bi; __syncthreads();
        for (int off=128; off; off>>=1){
            if (tid < off){
                if (rv[tid+off] > rv[tid] || (rv[tid+off]==rv[tid] && ri[tid+off]<ri[tid])){
                    rv[tid]=rv[tid+off]; ri[tid]=ri[tid+off];
                }
            }
            __syncthreads();
        }
        if (tid==0){ wv[it]=rv[0]; dv[it]=ri[0]; corr[ri[0]] = -1e30f; }
        __syncthreads();
    }
    if (tid==0){
        float mx = wv[0];
        float ex[TOPK]; float s=0.f;
        for (int i=0;i<TOPK;i++){ ex[i]=expf(wv[i]-mx); s+=ex[i]; }
        for (int i=0;i<TOPK;i++){ wout[b*8+i]=ex[i]/s; dout[b*8+i]=dv[i]; }
    }
}

// ---------------- roll & weight + residual (float4) ----------------
__global__ void roll_res_k(const float* __restrict__ P, const float* __restrict__ w,
                           const int* __restrict__ d, const float* __restrict__ res,
                           float* __restrict__ out){
    int idx = blockIdx.x*256 + threadIdx.x;
    if (idx >= BLD/4) return;
    int c4 = idx & 127;
    int t = (idx >> 7) & (LL-1);
    int b = idx >> 17;
    float4 s = __ldg(&((const float4*)res)[idx]);
#pragma unroll
    for (int i=0;i<TOPK;i++){
        int   dl = __ldg(&d[b*8+i]);
        float wi = __ldg(&w[b*8+i]);
        int tt = (t + dl) & (LL-1);
        float4 v = __ldg(&((const float4*)P)[((size_t)(b*LL + tt) << 7) + c4]);
        s.x += wi*v.x; s.y += wi*v.y; s.z += wi*v.z; s.w += wi*v.w;
    }
    ((float4*)out)[idx] = s;
}

// ---------------- series decomposition, scalar (for CIN channels) ----------------
__global__ void decomp_k(const float* __restrict__ x, float* __restrict__ seas,
                         float* __restrict__ trend, int C, int mode,
                         bf16* __restrict__ oh, bf16* __restrict__ ol){
    int b = blockIdx.z;
    int c = blockIdx.x*blockDim.x + threadIdx.x;
    if (c >= C) return;
    int l0 = blockIdx.y * 128;
    const float* xb = x + (size_t)b*LL*C + c;
    float sum = 0.f;
    for (int j=l0-12;j<=l0+12;j++){
        int jj = min(max(j,0), LL-1);
        sum += xb[(size_t)jj*C];
    }
    for (int l=l0; l<l0+128; l++){
        float m = sum * (1.0f/25.0f);
        size_t o = (size_t)b*LL*C + (size_t)l*C + c;
        float sv = x[o] - m;
        seas[o] = sv;
        if (oh){ bf16 h,lo; bsplit(sv,h,lo); oh[o]=h; ol[o]=lo; }
        if (mode==1) trend[o] = m;
        else if (mode==2) trend[o] += m;
        int ja = min(l+13, LL-1), jr = max(l-12, 0);
        sum += xb[(size_t)ja*C] - xb[(size_t)jr*C];
    }
}

// ---------------- series decomposition, float4 (C = DD = 512) ----------------
__global__ void decomp4_k(const float* __restrict__ xf, float* __restrict__ seasf,
                          float* __restrict__ trendf, int mode,
                          bf16* __restrict__ oh, bf16* __restrict__ ol){
    const float4* x = (const float4*)xf;
    float4* seas = (float4*)seasf;
    float4* trend = (float4*)trendf;
    __nv_bfloat162* oh2 = (__nv_bfloat162*)oh;
    __nv_bfloat162* ol2 = (__nv_bfloat162*)ol;
    int b = blockIdx.z;
    int c4 = threadIdx.x;                 // 0..127
    int l0 = blockIdx.y * 64;
    const float4* xb = x + (size_t)b*LL*128 + c4;
    float4 sum = make_float4(0.f,0.f,0.f,0.f);
    for (int j=l0-12;j<=l0+12;j++){
        int jj = min(max(j,0), LL-1);
        float4 v = xb[(size_t)jj*128];
        sum.x+=v.x; sum.y+=v.y; sum.z+=v.z; sum.w+=v.w;
    }
    for (int l=l0; l<l0+64; l++){
        const float inv = 1.0f/25.0f;
        float4 m = make_float4(sum.x*inv, sum.y*inv, sum.z*inv, sum.w*inv);
        size_t o = (size_t)b*LL*128 + (size_t)l*128 + c4;
        float4 xv = xb[(size_t)l*128];
        float4 sv = make_float4(xv.x-m.x, xv.y-m.y, xv.z-m.z, xv.w-m.w);
        seas[o] = sv;
        if (oh){
            bf16 h0,lo0,h1,lo1,h2,lo2,h3,lo3;
            bsplit(sv.x,h0,lo0); bsplit(sv.y,h1,lo1);
            bsplit(sv.z,h2,lo2); bsplit(sv.w,h3,lo3);
            __nv_bfloat162 a,bb2;
            a.x=h0; a.y=h1; bb2.x=h2; bb2.y=h3;
            oh2[2*o]=a; oh2[2*o+1]=bb2;
            a.x=lo0; a.y=lo1; bb2.x=lo2; bb2.y=lo3;
            ol2[2*o]=a; ol2[2*o+1]=bb2;
        }
        if (mode==1) trend[o] = m;
        else if (mode==2){
            float4 t = trend[o];
            trend[o] = make_float4(t.x+m.x, t.y+m.y, t.z+m.z, t.w+m.w);
        }
        int ja = min(l+13, LL-1), jr = max(l-12, 0);
        float4 va = xb[(size_t)ja*128], vr = xb[(size_t)jr*128];
        sum.x += va.x - vr.x; sum.y += va.y - vr.y;
        sum.z += va.z - vr.z; sum.w += va.w - vr.w;
    }
}

// ---------------- layernorm over feature dim ----------------
__global__ void ln_k(const float* __restrict__ x, const float* __restrict__ w,
                     const float* __restrict__ bv, float* __restrict__ y){
    __shared__ float red[256];
    int row = blockIdx.x, tid = threadIdx.x;
    const float* xr = x + (size_t)row*DD;
    float v0 = xr[tid], v1 = xr[tid+256];
    red[tid] = v0+v1; __syncthreads();
    for (int o=128;o;o>>=1){ if (tid<o) red[tid]+=red[tid+o]; __syncthreads(); }
    float mu = red[0]*(1.0f/512.0f);
    __syncthreads();
    float d0=v0-mu, d1=v1-mu;
    red[tid] = d0*d0+d1*d1; __syncthreads();
    for (int o=128;o;o>>=1){ if (tid<o) red[tid]+=red[tid+o]; __syncthreads(); }
    float rstd = rsqrtf(red[0]*(1.0f/512.0f) + 1e-5f);
    y[(size_t)row*DD + tid]     = d0*rstd*w[tid]     + bv[tid];
    y[(size_t)row*DD + tid+256] = d1*rstd*w[tid+256] + bv[tid+256];
}

// ---------------- column (time) mean ----------------
__global__ void zero_k(float* p, int n){
    int i = blockIdx.x*blockDim.x + threadIdx.x;
    if (i < n) p[i] = 0.0f;
}
__global__ void colsum_k(const float* __restrict__ x, float* __restrict__ cm){
    int b = blockIdx.z;
    int c = blockIdx.x*256 + threadIdx.x;
    int l0 = blockIdx.y*128;
    float s=0.f;
    for (int l=l0;l<l0+128;l++) s += x[((size_t)b*LL + l)*DD + c];
    atomicAdd(&cm[b*DD + c], s);
}
__global__ void colsub_k(const float* __restrict__ x, const float* __restrict__ cm,
                         float* __restrict__ y, bf16* __restrict__ oh, bf16* __restrict__ ol){
    int idx = blockIdx.x*256 + threadIdx.x;
    if (idx >= BLD/4) return;
    int c4 = idx & 127;
    int b = idx >> 17;
    float4 xv = __ldg(&((const float4*)x)[idx]);
    float4 cv = __ldg(&((const float4*)cm)[b*128 + c4]);
    float4 v;
    v.x = xv.x - cv.x*(1.0f/1024.0f);
    v.y = xv.y - cv.y*(1.0f/1024.0f);
    v.z = xv.z - cv.z*(1.0f/1024.0f);
    v.w = xv.w - cv.w*(1.0f/1024.0f);
    ((float4*)y)[idx] = v;
    if (oh){
        bf16 h0,l0,h1,l1,h2,l2,h3,l3;
        bsplit(v.x,h0,l0); bsplit(v.y,h1,l1); bsplit(v.z,h2,l2); bsplit(v.w,h3,l3);
        __nv_bfloat162* oh2 = (__nv_bfloat162*)oh;
        __nv_bfloat162* ol2 = (__nv_bfloat162*)ol;
        __nv_bfloat162 a,bb2;
        a.x=h0; a.y=h1; bb2.x=h2; bb2.y=h3;
        oh2[2*idx]=a; oh2[2*idx+1]=bb2;
        a.x=l0; a.y=l1; bb2.x=l2; bb2.y=l3;
        ol2[2*idx]=a; ol2[2*idx+1]=bb2;
    }
}

// ---------------- embedding ----------------
__global__ void embed_k(const float* __restrict__ x, const float* __restrict__ mark,
                        const float* __restrict__ Wtok, const float* __restrict__ Wtem,
                        float* __restrict__ out, bf16* __restrict__ oh, bf16* __restrict__ ol){
    int d = blockIdx.x*256 + threadIdx.x;
    int b = blockIdx.z;
    int l0 = blockIdx.y*8;
    float w[21], wt[4];
#pragma unroll
    for (int i=0;i<21;i++) w[i] = __ldg(&Wtok[(size_t)i*DD + d]);
#pragma unroll
    for (int m=0;m<MK;m++) wt[m] = __ldg(&Wtem[(size_t)m*DD + d]);
#pragma unroll
    for (int i=0;i<8;i++){
        int l = l0 + i;
        int lm = (l + LL - 1) & (LL-1), lp = (l + 1) & (LL-1);
        const float* x0 = x + ((size_t)b*LL + lm)*CIN;
        const float* x1 = x + ((size_t)b*LL + l )*CIN;
        const float* x2 = x + ((size_t)b*LL + lp)*CIN;
        float s = 0.f;
#pragma unroll
        for (int c=0;c<CIN;c++){
            s += x0[c]*w[c];
            s += x1[c]*w[7+c];
            s += x2[c]*w[14+c];
        }
        const float* mk = mark + ((size_t)b*LL + l)*MK;
#pragma unroll
        for (int m=0;m<MK;m++) s += mk[m]*wt[m];
        size_t o = ((size_t)b*LL + l)*DD + d;
        out[o] = s;
        bf16 h,lo; bsplit(s,h,lo); oh[o]=h; ol[o]=lo;
    }
}

// ---------------- mean of x_enc over time ----------------
__global__ void meanenc_k(const float* __restrict__ x, float* __restrict__ m){
    __shared__ float red[256];
    int b = blockIdx.x / CIN, c = blockIdx.x % CIN;
    int tid = threadIdx.x;
    float s=0.f;
    for (int l=tid;l<LL;l+=256) s += x[((size_t)b*LL + l)*CIN + c];
    red[tid]=s; __syncthreads();
    for (int o=128;o;o>>=1){ if (tid<o) red[tid]+=red[tid+o]; __syncthreads(); }
    if (tid==0) m[blockIdx.x] = red[0]*(1.0f/1024.0f);
}

__global__ void decinit_k(const float* __restrict__ sx, const float* __restrict__ tx,
                          const float* __restrict__ menc, float* __restrict__ seas,
                          float* __restrict__ trend){
    int idx = blockIdx.x*256 + threadIdx.x;
    if (idx >= BL7) return;
    int c = idx % CIN;
    int l = (idx / CIN) % LL;
    int b = idx / (CIN*LL);
    if (l < 512){
        size_t src = ((size_t)b*LL + 512 + l)*CIN + c;
        seas[idx]  = sx[src];
        trend[idx] = tx[src];
    } else {
        seas[idx]  = 0.f;
        trend[idx] = menc[b*CIN + c];
    }
}

// ---------------- trend conv with transposed weights (float4 dots) ----------------
__global__ void trendconv_k(const float* __restrict__ t123, const float* __restrict__ Wt2,
                            float* __restrict__ trend){
    int idx = blockIdx.x*256 + threadIdx.x;
    if (idx >= BL7) return;
    int c = idx % CIN;
    int l = (idx / CIN) & (LL-1);
    int b = idx / (CIN*LL);
    int lm = (l + LL - 1) & (LL-1), lp = (l + 1) & (LL-1);
    const float4* r0 = (const float4*)(t123 + ((size_t)b*LL + lm)*DD);
    const float4* r1 = (const float4*)(t123 + ((size_t)b*LL + l )*DD);
    const float4* r2 = (const float4*)(t123 + ((size_t)b*LL + lp)*DD);
    const float4* w0 = (const float4*)(Wt2 + (size_t)c*3*DD);
    const float4* w1 = w0 + 128;
    const float4* w2 = w0 + 256;
    float s = 0.f;
    for (int d4=0; d4<128; d4++){
        float4 a = __ldg(r0+d4), wa = __ldg(w0+d4);
        s += a.x*wa.x + a.y*wa.y + a.z*wa.z + a.w*wa.w;
        float4 bv = __ldg(r1+d4), wb = __ldg(w1+d4);
        s += bv.x*wb.x + bv.y*wb.y + bv.z*wb.z + bv.w*wb.w;
        float4 cv = __ldg(r2+d4), wc = __ldg(w2+d4);
        s += cv.x*wc.x + cv.y*wc.y + cv.z*wc.z + cv.w*wc.w;
    }
    trend[idx] += s;
}

// ---------------- final projection with transposed weights ----------------
__global__ void final_k(const float* __restrict__ dec, const float* __restrict__ pw2,
                        const float* __restrict__ projb, const float* __restrict__ trend,
                        float* __restrict__ out){
    int idx = blockIdx.x*256 + threadIdx.x;
    if (idx >= BB*512*CIN) return;
    int c = idx % CIN;
    int lp = (idx / CIN) % 512;
    int b = idx / (512*CIN);
    int l = 512 + lp;
    const float4* r = (const float4*)(dec + ((size_t)b*LL + l)*DD);
    const float4* w = (const float4*)(pw2 + (size_t)c*DD);
    float s = projb[c];
    for (int d4=0; d4<128; d4++){
        float4 a = __ldg(r+d4), wa = __ldg(w+d4);
        s += a.x*wa.x + a.y*wa.y + a.z*wa.z + a.w*wa.w;
    }
    out[idx] = trend[((size_t)b*LL + l)*CIN + c] + s;
}

// ---------------- host orchestration ----------------
static void gemm_tc(const bf16* ah, const bf16* al, const bf16* bh, const bf16* bl,
                    const float* bias, const float* res,
                    float* C, bf16* Ch, bf16* Cl, float* Ct, int N, int K, int gelu){
    dim3 g(N/128, MROWS/128);
    gemm_mma_k<<<g, 512, GEMM_SMEM>>>(ah, al, bh, bl, bias, res, C, Ch, Cl, Ct, N, K, gelu);
}

static void run_attn(int ai, const float* res,
                     const bf16* xqh, const bf16* xql,
                     const bf16* xkvh, const bf16* xkvl,
                     const float* bias, float* outb, float* Pv,
                     float* qt, float* kt, float2* Sp, float2* Sps,
                     float* wbuf, int* dbuf,
                     bf16* MH, bf16* ML, float* BVO4){
    gemm_tc(xqh, xql,  MH + (size_t)ai*DD*DD,     ML + (size_t)ai*DD*DD,
            bias,      nullptr, nullptr, nullptr, nullptr, qt, DD, DD, 0);
    gemm_tc(xkvh, xkvl, MH + (size_t)(4+ai)*DD*DD, ML + (size_t)(4+ai)*DD*DD,
            bias + DD, nullptr, nullptr, nullptr, nullptr, kt, DD, DD, 0);
    gemm_tc(xkvh, xkvl, MH + (size_t)(8+ai)*DD*DD, ML + (size_t)(8+ai)*DD*DD,
            BVO4 + ai*DD, nullptr, Pv, nullptr, nullptr, nullptr, DD, DD, 0);
    corr_fwd_k<<<dim3(BB*NH, 4), 256>>>(qt, kt, Sp);
    sumsp_k<<<dim3(8, BB), 128>>>(Sp, Sps);
    corr_topk_k<<<BB, 256>>>(Sps, wbuf, dbuf);
    roll_res_k<<<(BLD/4)/256, 256>>>(Pv, wbuf, dbuf, res, outb);
}

extern "C" void kernel_launch(void* const* d_in, const int* in_sizes, int n_in,
                              void* d_out, int out_size){
    const float* x_enc      = (const float*)d_in[0];
    const float* x_mark_enc = (const float*)d_in[1];
    const float* x_mark_dec = (const float*)d_in[3];
    const float* W_enc_tok  = (const float*)d_in[4];
    const float* W_enc_tem  = (const float*)d_in[5];
    const float* W_dec_tok  = (const float*)d_in[6];
    const float* W_dec_tem  = (const float*)d_in[7];
    const float* enc_attn_W = (const float*)d_in[8];
    const float* enc_attn_b = (const float*)d_in[9];
    const float* enc_ff1    = (const float*)d_in[10];
    const float* enc_ff2    = (const float*)d_in[11];
    const float* enc_ln_w   = (const float*)d_in[12];
    const float* enc_ln_b   = (const float*)d_in[13];
    const float* dec_self_W = (const float*)d_in[14];
    const float* dec_self_b = (const float*)d_in[15];
    const float* dec_cross_W= (const float*)d_in[16];
    const float* dec_cross_b= (const float*)d_in[17];
    const float* dec_ff1    = (const float*)d_in[18];
    const float* dec_ff2    = (const float*)d_in[19];
    const float* dec_trend_W= (const float*)d_in[20];
    const float* dec_ln_w   = (const float*)d_in[21];
    const float* dec_ln_b   = (const float*)d_in[22];
    const float* proj_W     = (const float*)d_in[23];
    const float* proj_b     = (const float*)d_in[24];
    float* out = (float*)d_out;

    cudaFuncSetAttribute(gemm_mma_k, cudaFuncAttributeMaxDynamicSharedMemorySize, GEMM_SMEM);

    void *pA,*pB,*pv,*penc,*pt123,*pqt,*pkt,*pSp,*pSps,*pcm,*pw,*pd;
    void *psx,*ptx,*pseas,*ptrd,*pmenc,*pwvo,*pbvo,*pwt2,*ppw2;
    void *ps1h,*ps1l,*pech,*pecl,*ps2h,*ps2l;
    void *pmh,*pml,*pf1h,*pf1l,*pf2h,*pf2l;
    cudaGetSymbolAddress(&pA, g_A);       cudaGetSymbolAddress(&pB, g_Bf);
    cudaGetSymbolAddress(&pv, g_v);       cudaGetSymbolAddress(&penc, g_enc);
    cudaGetSymbolAddress(&pt123, g_t123);
    cudaGetSymbolAddress(&pqt, g_qt);     cudaGetSymbolAddress(&pkt, g_kt);
    cudaGetSymbolAddress(&pSp, g_Sp);     cudaGetSymbolAddress(&pSps, g_sps);
    cudaGetSymbolAddress(&pcm, g_cm);
    cudaGetSymbolAddress(&pw, g_w);       cudaGetSymbolAddress(&pd, g_dly);
    cudaGetSymbolAddress(&psx, g_sx);     cudaGetSymbolAddress(&ptx, g_tx);
    cudaGetSymbolAddress(&pseas, g_seas); cudaGetSymbolAddress(&ptrd, g_trd);
    cudaGetSymbolAddress(&pmenc, g_menc);
    cudaGetSymbolAddress(&pwvo, g_wvo4);  cudaGetSymbolAddress(&pbvo, g_bvo4);
    cudaGetSymbolAddress(&pwt2, g_wt2);   cudaGetSymbolAddress(&ppw2, g_pw2);
    cudaGetSymbolAddress(&ps1h, g_s1h);   cudaGetSymbolAddress(&ps1l, g_s1l);
    cudaGetSymbolAddress(&pech, g_ench);  cudaGetSymbolAddress(&pecl, g_encl);
    cudaGetSymbolAddress(&ps2h, g_s2h);   cudaGetSymbolAddress(&ps2l, g_s2l);
    cudaGetSymbolAddress(&pmh, g_mh);     cudaGetSymbolAddress(&pml, g_ml);
    cudaGetSymbolAddress(&pf1h, g_f1h);   cudaGetSymbolAddress(&pf1l, g_f1l);
    cudaGetSymbolAddress(&pf2h, g_f2h);   cudaGetSymbolAddress(&pf2l, g_f2l);

    float *A_=(float*)pA, *B_=(float*)pB, *V=(float*)pv;
    float *ENC=(float*)penc, *T123=(float*)pt123, *QT=(float*)pqt, *KT=(float*)pkt;
    float2 *SP=(float2*)pSp, *SPS=(float2*)pSps;
    float *CM=(float*)pcm, *WW=(float*)pw; int *DL=(int*)pd;
    float *SX=(float*)psx, *TX=(float*)ptx, *SEAS=(float*)pseas, *TRD=(float*)ptrd, *MENC=(float*)pmenc;
    float *WVO4=(float*)pwvo, *BVO4=(float*)pbvo, *WT2=(float*)pwt2, *PW2=(float*)ppw2;
    bf16 *S1H=(bf16*)ps1h, *S1L=(bf16*)ps1l, *ECH=(bf16*)pech, *ECL=(bf16*)pecl;
    bf16 *S2H=(bf16*)ps2h, *S2L=(bf16*)ps2l;
    bf16 *MH=(bf16*)pmh, *ML=(bf16*)pml;
    bf16 *F1H=(bf16*)pf1h, *F1L=(bf16*)pf1l, *F2H=(bf16*)pf2h, *F2L=(bf16*)pf2l;

    // ---- batched weight prep ----
    P4 wb; wb.p[0]=enc_attn_W; wb.p[1]=enc_attn_W + (size_t)4*DD*DD;
           wb.p[2]=dec_self_W; wb.p[3]=dec_cross_W;
    P4 bb; bb.p[0]=enc_attn_b; bb.p[1]=enc_attn_b + 4*DD;
           bb.p[2]=dec_self_b; bb.p[3]=dec_cross_b;
    mmvo_b_k<<<dim3(16,16,4), dim3(32,8)>>>(wb, WVO4);
    biasvo_b_k<<<dim3(2,4), 256>>>(bb, wb, BVO4);
    split512b_k<<<dim3(16,16,12), dim3(32,8)>>>(wb, WVO4, MH, ML);
    P3 f1; f1.p[0]=enc_ff1; f1.p[1]=enc_ff1 + (size_t)DD*DFF; f1.p[2]=dec_ff1;
    P3 f2; f2.p[0]=enc_ff2; f2.p[1]=enc_ff2 + (size_t)DFF*DD; f2.p[2]=dec_ff2;
    splitffb_k<<<dim3(64,16,3), dim3(32,8)>>>(f1, F1H, F1L, DD, DFF);
    splitffb_k<<<dim3(16,64,3), dim3(32,8)>>>(f2, F2H, F2L, DFF, DD);
    wtr_k<<<(3*DD*CIN + CIN*DD + 255)/256, 256>>>(dec_trend_W, WT2, proj_W, PW2);

    // ---- decoder init tensors (from x_enc) ----
    decomp_k<<<dim3(1,8,BB), 32>>>(x_enc, SX, TX, CIN, 1, nullptr, nullptr);
    meanenc_k<<<BB*CIN, 256>>>(x_enc, MENC);
    decinit_k<<<(BL7+255)/256, 256>>>(SX, TX, MENC, SEAS, TRD);

    // ---- encoder ----
    embed_k<<<dim3(2, LL/8, BB), 256>>>(x_enc, x_mark_enc, W_enc_tok, W_enc_tem, A_, S1H, S1L);
    for (int l=0; l<2; l++){
        run_attn(l, A_, S1H, S1L, S1H, S1L,
                 enc_attn_b + (size_t)l*4*DD,
                 B_, V, QT, KT, SP, SPS, WW, DL, MH, ML, BVO4);
        decomp4_k<<<dim3(1,16,BB), 128>>>(B_, A_, nullptr, 0, S1H, S1L);
        gemm_tc(S1H, S1L, F1H + (size_t)l*DD*DFF, F1L + (size_t)l*DD*DFF,
                nullptr, nullptr, nullptr, S2H, S2L, nullptr, DFF, DD, 1);
        gemm_tc(S2H, S2L, F2H + (size_t)l*DFF*DD, F2L + (size_t)l*DFF*DD,
                nullptr, A_, B_, nullptr, nullptr, nullptr, DD, DFF, 0);
        decomp4_k<<<dim3(1,16,BB), 128>>>(B_, A_, nullptr, 0, S1H, S1L);
    }
    ln_k<<<MROWS, 256>>>(A_, enc_ln_w, enc_ln_b, B_);
    zero_k<<<(BB*DD+255)/256, 256>>>(CM, BB*DD);
    colsum_k<<<dim3(2,8,BB), 256>>>(B_, CM);
    colsub_k<<<(BLD/4)/256, 256>>>(B_, CM, ENC, ECH, ECL);

    // ---- decoder ----
    embed_k<<<dim3(2, LL/8, BB), 256>>>(SEAS, x_mark_dec, W_dec_tok, W_dec_tem, A_, S1H, S1L);
    run_attn(2, A_, S1H, S1L, S1H, S1L, dec_self_b,
             B_, V, QT, KT, SP, SPS, WW, DL, MH, ML, BVO4);
    decomp4_k<<<dim3(1,16,BB), 128>>>(B_, A_, T123, 1, S1H, S1L);
    run_attn(3, A_, S1H, S1L, ECH, ECL, dec_cross_b,
             B_, V, QT, KT, SP, SPS, WW, DL, MH, ML, BVO4);
    decomp4_k<<<dim3(1,16,BB), 128>>>(B_, A_, T123, 2, S1H, S1L);
    gemm_tc(S1H, S1L, F1H + (size_t)2*DD*DFF, F1L + (size_t)2*DD*DFF,
            nullptr, nullptr, nullptr, S2H, S2L, nullptr, DFF, DD, 1);
    gemm_tc(S2H, S2L, F2H + (size_t)2*DFF*DD, F2L + (size_t)2*DFF*DD,
            nullptr, A_, B_, nullptr, nullptr, nullptr, DD, DFF, 0);
    decomp4_k<<<dim3(1,16,BB), 128>>>(B_, A_, T123, 2, S1H, S1L);
    trendconv_k<<<(BL7+255)/256, 256>>>(T123, WT2, TRD);
    ln_k<<<MROWS, 256>>>(A_, dec_ln_w, dec_ln_b, B_);
    zero_k<<<(BB*DD+255)/256, 256>>>(CM, BB*DD);
    colsum_k<<<dim3(2,8,BB), 256>>>(B_, CM);
    colsub_k<<<(BLD/4)/256, 256>>>(B_, CM, A_, nullptr, nullptr);
    final_k<<<(BB*512*CIN+255)/256, 256>>>(A_, PW2, proj_b, TRD, out);
}

// round 14
// speedup vs baseline: 1.0066x; 1.0066x over previous
#include <cuda_runtime.h>
#include <cuda_bf16.h>
#include <math.h>

// ---------------- constants ----------------
#define BB   32
#define LL   1024
#define DD   512
#define NH   8
#define HE   64
#define DFF  2048
#define CIN  7
#define MK   4
#define MROWS (BB*LL)          // 32768
#define BLD  (BB*LL*DD)        // 16777216
#define BL7  (BB*LL*CIN)       // 229376
#define TOPK 6

typedef __nv_bfloat16 bf16;

// ---------------- device scratch ----------------
__device__ float g_A   [BLD];
__device__ float g_Bf  [BLD];
__device__ float g_v   [BLD];
__device__ float g_enc [BLD];
__device__ float g_t123[BLD];
__device__ float g_qt  [BLD];
__device__ float g_kt  [BLD];
__device__ float2 g_Sp [BB*NH*4*LL];
__device__ float2 g_sps[BB*LL];
__device__ float g_cm  [BB*DD];
__device__ float g_w   [BB*8];
__device__ int   g_dly [BB*8];
__device__ float g_sx  [BL7];
__device__ float g_tx  [BL7];
__device__ float g_seas[BL7];
__device__ float g_trd [BL7];
__device__ float g_menc[BB*CIN];
// fused V weights (4 attentions)
__device__ float g_wvo4[4*DD*DD];     // Wv @ Wo
__device__ float g_bvo4[4*DD];        // bv@Wo + bo
// bf16 split buffers
__device__ bf16 g_mh [12*DD*DD];      // splits: Wq^T[0..3], Wk^T[4..7], WVO^T[8..11]
__device__ bf16 g_ml [12*DD*DD];
__device__ bf16 g_f1h[3*DD*DFF];
__device__ bf16 g_f1l[3*DD*DFF];
__device__ bf16 g_f2h[3*DFF*DD];
__device__ bf16 g_f2l[3*DFF*DD];
__device__ bf16 g_s1h[MROWS*DD];
__device__ bf16 g_s1l[MROWS*DD];
__device__ bf16 g_ench[MROWS*DD];
__device__ bf16 g_encl[MROWS*DD];
__device__ bf16 g_s2h[MROWS*DFF];
__device__ bf16 g_s2l[MROWS*DFF];

struct P4 { const float* p[4]; };
struct P3 { const float* p[3]; };

// ---------------- helpers ----------------
__device__ __forceinline__ void bsplit(float x, bf16& h, bf16& l){
    h = __float2bfloat16(x);
    l = __float2bfloat16(x - __bfloat162float(h));
}
__device__ __forceinline__ unsigned su32(const void* p){
    return (unsigned)__cvta_generic_to_shared(p);
}
__device__ __forceinline__ void cpa16(unsigned dst, const void* src){
    asm volatile("cp.async.cg.shared.global [%0], [%1], 16;" :: "r"(dst), "l"(src));
}
__device__ __forceinline__ void cpa_commit(){
    asm volatile("cp.async.commit_group;" ::: "memory");
}
__device__ __forceinline__ void cpa_wait2(){
    asm volatile("cp.async.wait_group 2;" ::: "memory");
}
__device__ __forceinline__ void ldsm4(unsigned* r, unsigned addr){
    asm volatile("ldmatrix.sync.aligned.m8n8.x4.shared.b16 {%0,%1,%2,%3}, [%4];"
        : "=r"(r[0]), "=r"(r[1]), "=r"(r[2]), "=r"(r[3]) : "r"(addr));
}
__device__ __forceinline__ void mma16(float* d, const unsigned* a, unsigned b0, unsigned b1){
    asm volatile("mma.sync.aligned.m16n8k16.row.col.f32.bf16.bf16.f32 "
        "{%0,%1,%2,%3},{%4,%5,%6,%7},{%8,%9},{%0,%1,%2,%3};"
        : "+f"(d[0]), "+f"(d[1]), "+f"(d[2]), "+f"(d[3])
        : "r"(a[0]), "r"(a[1]), "r"(a[2]), "r"(a[3]), "r"(b0), "r"(b1));
}

// ---------------- split-bf16 mma.sync GEMM ----------------
#define RSTRIDE 80
#define AREA    10240
#define STAGEB  40960
#define GEMM_SMEM (3*STAGEB)
__global__ void __launch_bounds__(512,1) gemm_mma_k(
    const bf16* __restrict__ Ahp, const bf16* __restrict__ Alp,
    const bf16* __restrict__ Bhp, const bf16* __restrict__ Blp,
    const float* __restrict__ bias, const float* __restrict__ res,
    float* __restrict__ C, bf16* __restrict__ Ch, bf16* __restrict__ Cl,
    float* __restrict__ Ct,
    int N, int K, int dogelu)
{
    extern __shared__ __align__(16) char dsm[];
    const int tid = threadIdx.x;
    const int lane = tid & 31, warp = tid >> 5;
    const int wm = warp >> 2, wn = warp & 3;
    const int bx = blockIdx.x, by = blockIdx.y;
    const int S = K >> 5;
    const unsigned sbase = su32(dsm);

    const int lrow = tid >> 2, lc16 = tid & 3;
    const bf16* gA_h = Ahp + (size_t)(by*128 + lrow)*K;
    const bf16* gA_l = Alp + (size_t)(by*128 + lrow)*K;
    const bf16* gB_h = Bhp + (size_t)(bx*128 + lrow)*K;
    const bf16* gB_l = Blp + (size_t)(bx*128 + lrow)*K;
    const unsigned sdst = lrow*RSTRIDE + lc16*16;

    float acc[2][4][4];
#pragma unroll
    for (int i=0;i<2;i++)
#pragma unroll
        for (int j=0;j<4;j++)
#pragma unroll
            for (int t=0;t<4;t++) acc[i][j][t]=0.f;

#pragma unroll
    for (int p=0;p<3;p++){
        if (p < S){
            unsigned b = sbase + p*STAGEB + sdst;
            int gk = p*32 + lc16*8;
            cpa16(b,            gA_h + gk);
            cpa16(b + AREA,     gA_l + gk);
            cpa16(b + 2*AREA,   gB_h + gk);
            cpa16(b + 3*AREA,   gB_l + gk);
        }
        cpa_commit();
    }

    const unsigned arow = (wm*32 + (lane & 15))*RSTRIDE + (lane >> 4)*16;
    const unsigned brow = (wn*32 + (lane & 15))*RSTRIDE + (lane >> 4)*16;

    for (int s=0; s<S; s++){
        cpa_wait2();
        __syncthreads();
        const unsigned sb = sbase + (s % 3)*STAGEB;
#pragma unroll
        for (int k16=0; k16<2; k16++){
            const unsigned ko = k16*32;
            unsigned ah[8], al[8], bh[8], bl[8];
            ldsm4(ah,   sb + arow + ko);
            ldsm4(ah+4, sb + arow + ko + 16*RSTRIDE);
            ldsm4(al,   sb + AREA + arow + ko);
            ldsm4(al+4, sb + AREA + arow + ko + 16*RSTRIDE);
            ldsm4(bh,   sb + 2*AREA + brow + ko);
            ldsm4(bh+4, sb + 2*AREA + brow + ko + 16*RSTRIDE);
            ldsm4(bl,   sb + 3*AREA + brow + ko);
            ldsm4(bl+4, sb + 3*AREA + brow + ko + 16*RSTRIDE);
#pragma unroll
            for (int mf=0; mf<2; mf++){
#pragma unroll
                for (int nf=0; nf<4; nf++){
                    int g = (nf>>1)*4 + (nf&1);
                    mma16(acc[mf][nf], ah+mf*4, bh[g], bh[g+2]);
                    mma16(acc[mf][nf], ah+mf*4, bl[g], bl[g+2]);
                    mma16(acc[mf][nf], al+mf*4, bh[g], bh[g+2]);
                }
            }
        }
        __syncthreads();
        if (s+3 < S){
            unsigned b = sbase + (s % 3)*STAGEB + sdst;
            int gk = (s+3)*32 + lc16*8;
            cpa16(b,            gA_h + gk);
            cpa16(b + AREA,     gA_l + gk);
            cpa16(b + 2*AREA,   gB_h + gk);
            cpa16(b + 3*AREA,   gB_l + gk);
        }
        cpa_commit();
    }

    if (Ct){
        float* st = (float*)dsm;  // [128 cols][129]
#pragma unroll
        for (int mf=0; mf<2; mf++){
#pragma unroll
            for (int nf=0; nf<4; nf++){
                int rl = wm*32 + mf*16 + (lane>>2);
                int cl = wn*32 + nf*8 + ((lane&3)<<1);
                float* d = acc[mf][nf];
#pragma unroll
                for (int h=0; h<2; h++){
                    float b0 = bias ? __ldg(&bias[bx*128 + cl])   : 0.f;
                    float b1 = bias ? __ldg(&bias[bx*128 + cl+1]) : 0.f;
                    st[cl*129 + rl + 8*h]     = d[2*h]   + b0;
                    st[(cl+1)*129 + rl + 8*h] = d[2*h+1] + b1;
                }
            }
        }
        __syncthreads();
        int gr = by*128;
        int b  = gr >> 10;
        int l0 = gr & 1023;
#pragma unroll
        for (int cc=0; cc<8; cc++){
            int col = warp*8 + cc;
            size_t rowoff = ((size_t)b*DD + bx*128 + col)*LL + l0;
#pragma unroll
            for (int i=0;i<4;i++){
                int r = lane + i*32;
                Ct[rowoff + r] = st[col*129 + r];
            }
        }
        return;
    }

#pragma unroll
    for (int mf=0; mf<2; mf++){
#pragma unroll
        for (int nf=0; nf<4; nf++){
            int r0  = by*128 + wm*32 + mf*16 + (lane>>2);
            int col = bx*128 + wn*32 + nf*8 + ((lane&3)<<1);
            float* d = acc[mf][nf];
#pragma unroll
            for (int h=0; h<2; h++){
                int r = r0 + h*8;
                size_t rowoff = (size_t)r * N;
                float2 o = make_float2(d[2*h], d[2*h+1]);
                if (bias){ o.x += __ldg(&bias[col]); o.y += __ldg(&bias[col+1]); }
                if (dogelu){
                    o.x = 0.5f*o.x*(1.0f+erff(o.x*0.7071067811865476f));
                    o.y = 0.5f*o.y*(1.0f+erff(o.y*0.7071067811865476f));
                }
                if (res){
                    float2 rr = *(const float2*)&res[rowoff + col];
                    o.x += rr.x; o.y += rr.y;
                }
                if (Ch){
                    bf16 h0,l0,h1,l1;
                    bsplit(o.x,h0,l0); bsplit(o.y,h1,l1);
                    __nv_bfloat162 hv; hv.x=h0; hv.y=h1;
                    __nv_bfloat162 lv; lv.x=l0; lv.y=l1;
                    *(__nv_bfloat162*)&Ch[rowoff + col] = hv;
                    *(__nv_bfloat162*)&Cl[rowoff + col] = lv;
                } else {
                    *(float2*)&C[rowoff + col] = o;
                }
            }
        }
    }
}

// ---------------- batched 512x512 matmuls: WVO[z] = Wv @ Wo ----------------
__global__ void mmvo_b_k(P4 wb, float* __restrict__ wvo){
    __shared__ float As[32][33], Bs[32][33];
    int z = blockIdx.z;
    const float* A = wb.p[z] + (size_t)2*DD*DD;
    const float* B = wb.p[z] + (size_t)3*DD*DD;
    float* C = wvo + (size_t)z*DD*DD;
    int i0 = blockIdx.y*32, j0 = blockIdx.x*32;
    int tx = threadIdx.x, ty = threadIdx.y;
    float acc[4] = {0.f,0.f,0.f,0.f};
    for (int k0=0;k0<512;k0+=32){
        for (int r=ty;r<32;r+=8){
            As[r][tx] = A[(size_t)(i0+r)*512 + k0+tx];
            Bs[r][tx] = B[(size_t)(k0+r)*512 + j0+tx];
        }
        __syncthreads();
#pragma unroll
        for (int k=0;k<32;k++){
            float bv = Bs[k][tx];
#pragma unroll
            for (int u=0;u<4;u++) acc[u] += As[ty+8*u][k]*bv;
        }
        __syncthreads();
    }
#pragma unroll
    for (int u=0;u<4;u++) C[(size_t)(i0+ty+8*u)*512 + j0+tx] = acc[u];
}

// ---------------- batched fused bias: bvo[z] = bv@Wo + bo ----------------
__global__ void biasvo_b_k(P4 bb, P4 wb, float* __restrict__ bvo){
    int z = blockIdx.y;
    int j = blockIdx.x*256 + threadIdx.x;
    if (j >= 512) return;
    const float* bv = bb.p[z] + 2*DD;
    const float* bo = bb.p[z] + 3*DD;
    const float* Wo = wb.p[z] + (size_t)3*DD*DD;
    float s = bo[j];
    for (int m=0;m<512;m++) s += bv[m]*Wo[(size_t)m*512 + j];
    bvo[z*DD + j] = s;
}

// ---------------- batched split+transpose of 12 512x512 mats ----------------
__global__ void split512b_k(P4 wb, const float* __restrict__ wvo,
                            bf16* __restrict__ oh, bf16* __restrict__ ol){
    __shared__ float t[32][33];
    int z = blockIdx.z;
    const float* W;
    if (z < 4)       W = wb.p[z];
    else if (z < 8)  W = wb.p[z-4] + (size_t)DD*DD;
    else             W = wvo + (size_t)(z-8)*DD*DD;
    bf16* ohp = oh + (size_t)z*DD*DD;
    bf16* olp = ol + (size_t)z*DD*DD;
    int n0 = blockIdx.x*32, k0 = blockIdx.y*32;
    int x = threadIdx.x, y = threadIdx.y;
    for (int i=y;i<32;i+=8)
        t[i][x] = W[(size_t)(k0+i)*DD + n0 + x];
    __syncthreads();
    for (int i=y;i<32;i+=8){
        float v = t[x][i];
        bf16 h,l; bsplit(v,h,l);
        ohp[(size_t)(n0+i)*DD + k0 + x] = h;
        olp[(size_t)(n0+i)*DD + k0 + x] = l;
    }
}

// ---------------- batched split+transpose for FF weights ----------------
__global__ void splitffb_k(P3 Wl, bf16* __restrict__ oh, bf16* __restrict__ ol,
                           int Kd, int Nd){
    __shared__ float t[32][33];
    int z = blockIdx.z;
    const float* W = Wl.p[z];
    bf16* ohp = oh + (size_t)z*Kd*Nd;
    bf16* olp = ol + (size_t)z*Kd*Nd;
    int n0 = blockIdx.x*32, k0 = blockIdx.y*32;
    int x = threadIdx.x, y = threadIdx.y;
    for (int i=y;i<32;i+=8)
        t[i][x] = W[(size_t)(k0+i)*Nd + n0 + x];
    __syncthreads();
    for (int i=y;i<32;i+=8){
        float v = t[x][i];
        bf16 h,l; bsplit(v,h,l);
        ohp[(size_t)(n0+i)*Kd + k0 + x] = h;
        olp[(size_t)(n0+i)*Kd + k0 + x] = l;
    }
}

// ---------------- FFT helpers ----------------
__device__ __forceinline__ float2 cmul(float2 a, float2 b){
    return make_float2(a.x*b.x - a.y*b.y, a.x*b.y + a.y*b.x);
}
__device__ __forceinline__ int dig4rev(int t){
    int br = __brev(t) >> 22;
    return ((br >> 1) & 0x155) | ((br << 1) & 0x2AA);
}
__device__ void fft1024_r4(float2* z, const float2* tw, int tid, int inv){
    const float s4 = inv ? 1.0f : -1.0f;
#pragma unroll
    for (int s=0; s<5; s++){
        __syncthreads();
        const int quarter = 1 << (2*s);
        const int pos = tid & (quarter-1);
        const int g   = tid >> (2*s);
        const int base = (g << (2*s+2)) + pos;
        const int tstep = pos << (8 - 2*s);
        float2 x0 = z[base];
        float2 x1 = cmul(tw[tstep],   z[base + quarter]);
        float2 x2 = cmul(tw[2*tstep], z[base + 2*quarter]);
        float2 x3 = cmul(tw[3*tstep], z[base + 3*quarter]);
        float2 t0 = make_float2(x0.x+x2.x, x0.y+x2.y);
        float2 t1 = make_float2(x0.x-x2.x, x0.y-x2.y);
        float2 t2 = make_float2(x1.x+x3.x, x1.y+x3.y);
        float2 t3 = make_float2(x1.x-x3.x, x1.y-x3.y);
        float2 rot = make_float2(-s4*t3.y, s4*t3.x);
        z[base]             = make_float2(t0.x+t2.x, t0.y+t2.y);
        z[base+quarter]     = make_float2(t1.x+rot.x, t1.y+rot.y);
        z[base+2*quarter]   = make_float2(t0.x-t2.x, t0.y-t2.y);
        z[base+3*quarter]   = make_float2(t1.x-rot.x, t1.y-rot.y);
    }
    __syncthreads();
}

#define EPB 16
__global__ void corr_fwd_k(const float* __restrict__ qt, const float* __restrict__ kt,
                           float2* __restrict__ Sp){
    __shared__ float2 z[1024];
    __shared__ float2 acc[1024];
    __shared__ float2 tw[1024];
    int bh = blockIdx.x;
    int chunk = blockIdx.y;
    int tid = threadIdx.x;
    for (int j=tid;j<1024;j+=256){
        float s,c; sincosf((float)j * (6.283185307179586f/1024.0f), &s, &c);
        tw[j] = make_float2(c, -s);
    }
    for (int f=tid;f<1024;f+=256) acc[f] = make_float2(0.f,0.f);
    for (int ei=0; ei<EPB; ei++){
        int e = chunk*EPB + ei;
        const float* qp = qt + ((size_t)bh*HE + e)*LL;
        const float* kp = kt + ((size_t)bh*HE + e)*LL;
        __syncthreads();
        for (int t=tid;t<1024;t+=256){
            z[dig4rev(t)] = make_float2(qp[t], kp[t]);
        }
        fft1024_r4(z, tw, tid, 0);
        for (int f=tid;f<1024;f+=256){
            float2 Zf = z[f];
            float2 Zm = z[(1024 - f) & 1023];
            float2 Zc = make_float2(Zm.x, -Zm.y);
            float2 Q  = make_float2(0.5f*(Zf.x+Zc.x), 0.5f*(Zf.y+Zc.y));
            float dx = Zf.x - Zc.x, dy = Zf.y - Zc.y;
            float2 Kk = make_float2(0.5f*dy, -0.5f*dx);
            acc[f].x += Q.x*Kk.x + Q.y*Kk.y;
            acc[f].y += Q.y*Kk.x - Q.x*Kk.y;
        }
    }
    __syncthreads();
    float2* dst = Sp + ((size_t)bh*4 + chunk)*LL;
    for (int f=tid;f<1024;f+=256) dst[f] = acc[f];
}

// ---------------- sum the 32 partial spectra per batch ----------------
__global__ void sumsp_k(const float2* __restrict__ Sp, float2* __restrict__ Sps){
    int b = blockIdx.y;
    int f = blockIdx.x*128 + threadIdx.x;
    float sx=0.f, sy=0.f;
    const float2* sp = Sp + (size_t)b*32*LL + f;
#pragma unroll
    for (int sl=0;sl<32;sl++){
        float2 v = sp[(size_t)sl*LL];
        sx += v.x; sy += v.y;
    }
    Sps[(size_t)b*LL + f] = make_float2(sx, sy);
}

__global__ void corr_topk_k(const float2* __restrict__ Sps, float* __restrict__ wout,
                            int* __restrict__ dout){
    __shared__ float2 z[1024];
    __shared__ float2 tw[1024];
    __shared__ float corr[1024];
    __shared__ float rv[256];
    __shared__ int   ri[256];
    __shared__ float wv[TOPK];
    __shared__ int   dv[TOPK];
    int b = blockIdx.x, tid = threadIdx.x;
    for (int j=tid;j<1024;j+=256){
        float s,c; sincosf((float)j * (6.283185307179586f/1024.0f), &s, &c);
        tw[j] = make_float2(c, s);
    }
    for (int f=tid;f<1024;f+=256){
        z[dig4rev(f)] = Sps[(size_t)b*LL + f];
    }
    fft1024_r4(z, tw, tid, 1);
    const float scale = 1.0f / (1024.0f * 512.0f);
    for (int f=tid;f<1024;f+=256) corr[f] = z[f].x * scale;
    __syncthreads();
    for (int it=0; it<TOPK; it++){
        float best = -1e30f; int bi = 1<<30;
        for (int f=tid;f<1024;f+=256){
            float v = corr[f];
            if (v > best || (v == best && f < bi)){ best = v; bi = f; }
        }
        rv[tid]=best; ri[tid]=bi; __syncthreads();
        for (int off=128; off; off>>=1){
            if (tid < off){
                if (rv[tid+off] > rv[tid] || (rv[tid+off]==rv[tid] && ri[tid+off]<ri[tid])){
                    rv[tid]=rv[tid+off]; ri[tid]=ri[tid+off];
                }
            }
            __syncthreads();
        }
        if (tid==0){ wv[it]=rv[0]; dv[it]=ri[0]; corr[ri[0]] = -1e30f; }
        __syncthreads();
    }
    if (tid==0){
        float mx = wv[0];
        float ex[TOPK]; float s=0.f;
        for (int i=0;i<TOPK;i++){ ex[i]=expf(wv[i]-mx); s+=ex[i]; }
        for (int i=0;i<TOPK;i++){ wout[b*8+i]=ex[i]/s; dout[b*8+i]=dv[i]; }
    }
}

// ---------------- roll & weight + residual (float4) ----------------
__global__ void roll_res_k(const float* __restrict__ P, const float* __restrict__ w,
                           const int* __restrict__ d, const float* __restrict__ res,
                           float* __restrict__ out){
    int idx = blockIdx.x*256 + threadIdx.x;
    if (idx >= BLD/4) return;
    int c4 = idx & 127;
    int t = (idx >> 7) & (LL-1);
    int b = idx >> 17;
    float4 s = __ldg(&((const float4*)res)[idx]);
#pragma unroll
    for (int i=0;i<TOPK;i++){
        int   dl = __ldg(&d[b*8+i]);
        float wi = __ldg(&w[b*8+i]);
        int tt = (t + dl) & (LL-1);
        float4 v = __ldg(&((const float4*)P)[((size_t)(b*LL + tt) << 7) + c4]);
        s.x += wi*v.x; s.y += wi*v.y; s.z += wi*v.z; s.w += wi*v.w;
    }
    ((float4*)out)[idx] = s;
}

// ---------------- series decomposition (moving mean k=25) ----------------
__global__ void decomp_k(const float* __restrict__ x, float* __restrict__ seas,
                         float* __restrict__ trend, int C, int mode,
                         bf16* __restrict__ oh, bf16* __restrict__ ol){
    int b = blockIdx.z;
    int c = blockIdx.x*blockDim.x + threadIdx.x;
    if (c >= C) return;
    int l0 = blockIdx.y * 128;
    const float* xb = x + (size_t)b*LL*C + c;
    float sum = 0.f;
    for (int j=l0-12;j<=l0+12;j++){
        int jj = min(max(j,0), LL-1);
        sum += xb[(size_t)jj*C];
    }
    for (int l=l0; l<l0+128; l++){
        float m = sum * (1.0f/25.0f);
        size_t o = (size_t)b*LL*C + (size_t)l*C + c;
        float sv = x[o] - m;
        seas[o] = sv;
        if (oh){ bf16 h,lo; bsplit(sv,h,lo); oh[o]=h; ol[o]=lo; }
        if (mode==1) trend[o] = m;
        else if (mode==2) trend[o] += m;
        int ja = min(l+13, LL-1), jr = max(l-12, 0);
        sum += xb[(size_t)ja*C] - xb[(size_t)jr*C];
    }
}

// ---------------- layernorm over feature dim ----------------
__global__ void ln_k(const float* __restrict__ x, const float* __restrict__ w,
                     const float* __restrict__ bv, float* __restrict__ y){
    __shared__ float red[256];
    int row = blockIdx.x, tid = threadIdx.x;
    const float* xr = x + (size_t)row*DD;
    float v0 = xr[tid], v1 = xr[tid+256];
    red[tid] = v0+v1; __syncthreads();
    for (int o=128;o;o>>=1){ if (tid<o) red[tid]+=red[tid+o]; __syncthreads(); }
    float mu = red[0]*(1.0f/512.0f);
    __syncthreads();
    float d0=v0-mu, d1=v1-mu;
    red[tid] = d0*d0+d1*d1; __syncthreads();
    for (int o=128;o;o>>=1){ if (tid<o) red[tid]+=red[tid+o]; __syncthreads(); }
    float rstd = rsqrtf(red[0]*(1.0f/512.0f) + 1e-5f);
    y[(size_t)row*DD + tid]     = d0*rstd*w[tid]     + bv[tid];
    y[(size_t)row*DD + tid+256] = d1*rstd*w[tid+256] + bv[tid+256];
}

// ---------------- column (time) mean ----------------
__global__ void zero_k(float* p, int n){
    int i = blockIdx.x*blockDim.x + threadIdx.x;
    if (i < n) p[i] = 0.0f;
}
__global__ void colsum_k(const float* __restrict__ x, float* __restrict__ cm){
    int b = blockIdx.z;
    int c = blockIdx.x*256 + threadIdx.x;
    int l0 = blockIdx.y*128;
    float s=0.f;
    for (int l=l0;l<l0+128;l++) s += x[((size_t)b*LL + l)*DD + c];
    atomicAdd(&cm[b*DD + c], s);
}
__global__ void colsub_k(const float* __restrict__ x, const float* __restrict__ cm,
                         float* __restrict__ y, bf16* __restrict__ oh, bf16* __restrict__ ol){
    int idx = blockIdx.x*256 + threadIdx.x;
    if (idx >= BLD/4) return;
    int c4 = idx & 127;
    int b = idx >> 17;
    float4 xv = __ldg(&((const float4*)x)[idx]);
    float4 cv = __ldg(&((const float4*)cm)[b*128 + c4]);
    float4 v;
    v.x = xv.x - cv.x*(1.0f/1024.0f);
    v.y = xv.y - cv.y*(1.0f/1024.0f);
    v.z = xv.z - cv.z*(1.0f/1024.0f);
    v.w = xv.w - cv.w*(1.0f/1024.0f);
    ((float4*)y)[idx] = v;
    if (oh){
        bf16 h0,l0,h1,l1,h2,l2,h3,l3;
        bsplit(v.x,h0,l0); bsplit(v.y,h1,l1); bsplit(v.z,h2,l2); bsplit(v.w,h3,l3);
        __nv_bfloat162* oh2 = (__nv_bfloat162*)oh;
        __nv_bfloat162* ol2 = (__nv_bfloat162*)ol;
        __nv_bfloat162 a,bb2;
        a.x=h0; a.y=h1; bb2.x=h2; bb2.y=h3;
        oh2[2*idx]=a; oh2[2*idx+1]=bb2;
        a.x=l0; a.y=l1; bb2.x=l2; bb2.y=l3;
        ol2[2*idx]=a; ol2[2*idx+1]=bb2;
    }
}

// ---------------- embedding (weight-register reuse, 8 l per thread) ----------------
__global__ void embed_k(const float* __restrict__ x, const float* __restrict__ mark,
                        const float* __restrict__ Wtok, const float* __restrict__ Wtem,
                        float* __restrict__ out, bf16* __restrict__ oh, bf16* __restrict__ ol){
    int d = blockIdx.x*256 + threadIdx.x;
    int b = blockIdx.z;
    int l0 = blockIdx.y*8;
    float w[21], wt[4];
#pragma unroll
    for (int i=0;i<21;i++) w[i] = __ldg(&Wtok[(size_t)i*DD + d]);
#pragma unroll
    for (int m=0;m<MK;m++) wt[m] = __ldg(&Wtem[(size_t)m*DD + d]);
#pragma unroll
    for (int i=0;i<8;i++){
        int l = l0 + i;
        int lm = (l + LL - 1) & (LL-1), lp = (l + 1) & (LL-1);
        const float* x0 = x + ((size_t)b*LL + lm)*CIN;
        const float* x1 = x + ((size_t)b*LL + l )*CIN;
        const float* x2 = x + ((size_t)b*LL + lp)*CIN;
        float s = 0.f;
#pragma unroll
        for (int c=0;c<CIN;c++){
            s += x0[c]*w[c];
            s += x1[c]*w[7+c];
            s += x2[c]*w[14+c];
        }
        const float* mk = mark + ((size_t)b*LL + l)*MK;
#pragma unroll
        for (int m=0;m<MK;m++) s += mk[m]*wt[m];
        size_t o = ((size_t)b*LL + l)*DD + d;
        out[o] = s;
        bf16 h,lo; bsplit(s,h,lo); oh[o]=h; ol[o]=lo;
    }
}

// ---------------- mean of x_enc over time ----------------
__global__ void meanenc_k(const float* __restrict__ x, float* __restrict__ m){
    __shared__ float red[256];
    int b = blockIdx.x / CIN, c = blockIdx.x % CIN;
    int tid = threadIdx.x;
    float s=0.f;
    for (int l=tid;l<LL;l+=256) s += x[((size_t)b*LL + l)*CIN + c];
    red[tid]=s; __syncthreads();
    for (int o=128;o;o>>=1){ if (tid<o) red[tid]+=red[tid+o]; __syncthreads(); }
    if (tid==0) m[blockIdx.x] = red[0]*(1.0f/1024.0f);
}

__global__ void decinit_k(const float* __restrict__ sx, const float* __restrict__ tx,
                          const float* __restrict__ menc, float* __restrict__ seas,
                          float* __restrict__ trend){
    int idx = blockIdx.x*256 + threadIdx.x;
    if (idx >= BL7) return;
    int c = idx % CIN;
    int l = (idx / CIN) % LL;
    int b = idx / (CIN*LL);
    if (l < 512){
        size_t src = ((size_t)b*LL + 512 + l)*CIN + c;
        seas[idx]  = sx[src];
        trend[idx] = tx[src];
    } else {
        seas[idx]  = 0.f;
        trend[idx] = menc[b*CIN + c];
    }
}

__global__ void trendconv_k(const float* __restrict__ t123, const float* __restrict__ Wt,
                            float* __restrict__ trend){
    int idx = blockIdx.x*256 + threadIdx.x;
    if (idx >= BL7) return;
    int c = idx % CIN;
    int l = (idx / CIN) % LL;
    int b = idx / (CIN*LL);
    int lm = (l + LL - 1) & (LL-1), lp = (l + 1) & (LL-1);
    const float* r0 = t123 + ((size_t)b*LL + lm)*DD;
    const float* r1 = t123 + ((size_t)b*LL + l )*DD;
    const float* r2 = t123 + ((size_t)b*LL + lp)*DD;
    float s = 0.f;
    for (int d=0; d<DD; d++){
        s += r0[d]*__ldg(&Wt[(0*DD+d)*CIN + c]);
        s += r1[d]*__ldg(&Wt[(1*DD+d)*CIN + c]);
        s += r2[d]*__ldg(&Wt[(2*DD+d)*CIN + c]);
    }
    trend[idx] += s;
}

__global__ void final_k(const float* __restrict__ dec, const float* __restrict__ projW,
                        const float* __restrict__ projb, const float* __restrict__ trend,
                        float* __restrict__ out){
    int idx = blockIdx.x*256 + threadIdx.x;
    if (idx >= BB*512*CIN) return;
    int c = idx % CIN;
    int lp = (idx / CIN) % 512;
    int b = idx / (512*CIN);
    int l = 512 + lp;
    const float* r = dec + ((size_t)b*LL + l)*DD;
    float s = projb[c];
    for (int d=0; d<DD; d++) s += r[d]*__ldg(&projW[d*CIN + c]);
    out[idx] = trend[((size_t)b*LL + l)*CIN + c] + s;
}

// ---------------- host orchestration ----------------
static void gemm_tc(cudaStream_t st,
                    const bf16* ah, const bf16* al, const bf16* bh, const bf16* bl,
                    const float* bias, const float* res,
                    float* C, bf16* Ch, bf16* Cl, float* Ct, int N, int K, int gelu){
    dim3 g(N/128, MROWS/128);
    gemm_mma_k<<<g, 512, GEMM_SMEM, st>>>(ah, al, bh, bl, bias, res, C, Ch, Cl, Ct, N, K, gelu);
}

static void run_attn(int ai, const float* res,
                     const bf16* xqh, const bf16* xql,
                     const bf16* xkvh, const bf16* xkvl,
                     const float* bias, float* outb, float* Pv,
                     float* qt, float* kt, float2* Sp, float2* Sps,
                     float* wbuf, int* dbuf,
                     bf16* MH, bf16* ML, float* BVO4,
                     cudaStream_t s2, cudaEvent_t ev1, cudaEvent_t ev2){
    gemm_tc(0, xqh, xql,  MH + (size_t)ai*DD*DD,     ML + (size_t)ai*DD*DD,
            bias,      nullptr, nullptr, nullptr, nullptr, qt, DD, DD, 0);
    gemm_tc(0, xkvh, xkvl, MH + (size_t)(4+ai)*DD*DD, ML + (size_t)(4+ai)*DD*DD,
            bias + DD, nullptr, nullptr, nullptr, nullptr, kt, DD, DD, 0);
    // fork: V*Wo GEMM on side stream, correlation chain on main stream
    cudaEventRecord(ev1, 0);
    cudaStreamWaitEvent(s2, ev1, 0);
    gemm_tc(s2, xkvh, xkvl, MH + (size_t)(8+ai)*DD*DD, ML + (size_t)(8+ai)*DD*DD,
            BVO4 + ai*DD, nullptr, Pv, nullptr, nullptr, nullptr, DD, DD, 0);
    cudaEventRecord(ev2, s2);
    corr_fwd_k<<<dim3(BB*NH, 4), 256>>>(qt, kt, Sp);
    sumsp_k<<<dim3(8, BB), 128>>>(Sp, Sps);
    corr_topk_k<<<BB, 256>>>(Sps, wbuf, dbuf);
    cudaStreamWaitEvent(0, ev2, 0);
    roll_res_k<<<(BLD/4)/256, 256>>>(Pv, wbuf, dbuf, res, outb);
}

extern "C" void kernel_launch(void* const* d_in, const int* in_sizes, int n_in,
                              void* d_out, int out_size){
    const float* x_enc      = (const float*)d_in[0];
    const float* x_mark_enc = (const float*)d_in[1];
    const float* x_mark_dec = (const float*)d_in[3];
    const float* W_enc_tok  = (const float*)d_in[4];
    const float* W_enc_tem  = (const float*)d_in[5];
    const float* W_dec_tok  = (const float*)d_in[6];
    const float* W_dec_tem  = (const float*)d_in[7];
    const float* enc_attn_W = (const float*)d_in[8];
    const float* enc_attn_b = (const float*)d_in[9];
    const float* enc_ff1    = (const float*)d_in[10];
    const float* enc_ff2    = (const float*)d_in[11];
    const float* enc_ln_w   = (const float*)d_in[12];
    const float* enc_ln_b   = (const float*)d_in[13];
    const float* dec_self_W = (const float*)d_in[14];
    const float* dec_self_b = (const float*)d_in[15];
    const float* dec_cross_W= (const float*)d_in[16];
    const float* dec_cross_b= (const float*)d_in[17];
    const float* dec_ff1    = (const float*)d_in[18];
    const float* dec_ff2    = (const float*)d_in[19];
    const float* dec_trend_W= (const float*)d_in[20];
    const float* dec_ln_w   = (const float*)d_in[21];
    const float* dec_ln_b   = (const float*)d_in[22];
    const float* proj_W     = (const float*)d_in[23];
    const float* proj_b     = (const float*)d_in[24];
    float* out = (float*)d_out;

    cudaFuncSetAttribute(gemm_mma_k, cudaFuncAttributeMaxDynamicSharedMemorySize, GEMM_SMEM);

    // streams/events: created once on the first (non-capture) call
    static cudaStream_t s2 = nullptr;
    static cudaEvent_t ev1 = nullptr, ev2 = nullptr;
    if (!s2){
        cudaStreamCreateWithFlags(&s2, cudaStreamNonBlocking);
        cudaEventCreateWithFlags(&ev1, cudaEventDisableTiming);
        cudaEventCreateWithFlags(&ev2, cudaEventDisableTiming);
    }

    void *pA,*pB,*pv,*penc,*pt123,*pqt,*pkt,*pSp,*pSps,*pcm,*pw,*pd;
    void *psx,*ptx,*pseas,*ptrd,*pmenc,*pwvo,*pbvo;
    void *ps1h,*ps1l,*pech,*pecl,*ps2h,*ps2l;
    void *pmh,*pml,*pf1h,*pf1l,*pf2h,*pf2l;
    cudaGetSymbolAddress(&pA, g_A);       cudaGetSymbolAddress(&pB, g_Bf);
    cudaGetSymbolAddress(&pv, g_v);       cudaGetSymbolAddress(&penc, g_enc);
    cudaGetSymbolAddress(&pt123, g_t123);
    cudaGetSymbolAddress(&pqt, g_qt);     cudaGetSymbolAddress(&pkt, g_kt);
    cudaGetSymbolAddress(&pSp, g_Sp);     cudaGetSymbolAddress(&pSps, g_sps);
    cudaGetSymbolAddress(&pcm, g_cm);
    cudaGetSymbolAddress(&pw, g_w);       cudaGetSymbolAddress(&pd, g_dly);
    cudaGetSymbolAddress(&psx, g_sx);     cudaGetSymbolAddress(&ptx, g_tx);
    cudaGetSymbolAddress(&pseas, g_seas); cudaGetSymbolAddress(&ptrd, g_trd);
    cudaGetSymbolAddress(&pmenc, g_menc);
    cudaGetSymbolAddress(&pwvo, g_wvo4);  cudaGetSymbolAddress(&pbvo, g_bvo4);
    cudaGetSymbolAddress(&ps1h, g_s1h);   cudaGetSymbolAddress(&ps1l, g_s1l);
    cudaGetSymbolAddress(&pech, g_ench);  cudaGetSymbolAddress(&pecl, g_encl);
    cudaGetSymbolAddress(&ps2h, g_s2h);   cudaGetSymbolAddress(&ps2l, g_s2l);
    cudaGetSymbolAddress(&pmh, g_mh);     cudaGetSymbolAddress(&pml, g_ml);
    cudaGetSymbolAddress(&pf1h, g_f1h);   cudaGetSymbolAddress(&pf1l, g_f1l);
    cudaGetSymbolAddress(&pf2h, g_f2h);   cudaGetSymbolAddress(&pf2l, g_f2l);

    float *A_=(float*)pA, *B_=(float*)pB, *V=(float*)pv;
    float *ENC=(float*)penc, *T123=(float*)pt123, *QT=(float*)pqt, *KT=(float*)pkt;
    float2 *SP=(float2*)pSp, *SPS=(float2*)pSps;
    float *CM=(float*)pcm, *WW=(float*)pw; int *DL=(int*)pd;
    float *SX=(float*)psx, *TX=(float*)ptx, *SEAS=(float*)pseas, *TRD=(float*)ptrd, *MENC=(float*)pmenc;
    float *WVO4=(float*)pwvo, *BVO4=(float*)pbvo;
    bf16 *S1H=(bf16*)ps1h, *S1L=(bf16*)ps1l, *ECH=(bf16*)pech, *ECL=(bf16*)pecl;
    bf16 *S2H=(bf16*)ps2h, *S2L=(bf16*)ps2l;
    bf16 *MH=(bf16*)pmh, *ML=(bf16*)pml;
    bf16 *F1H=(bf16*)pf1h, *F1L=(bf16*)pf1l, *F2H=(bf16*)pf2h, *F2L=(bf16*)pf2l;

    // ---- fork: weight prep on s2, input-side prep on stream 0 ----
    cudaEventRecord(ev1, 0);
    cudaStreamWaitEvent(s2, ev1, 0);

    P4 wb; wb.p[0]=enc_attn_W; wb.p[1]=enc_attn_W + (size_t)4*DD*DD;
           wb.p[2]=dec_self_W; wb.p[3]=dec_cross_W;
    P4 bb; bb.p[0]=enc_attn_b; bb.p[1]=enc_attn_b + 4*DD;
           bb.p[2]=dec_self_b; bb.p[3]=dec_cross_b;
    mmvo_b_k<<<dim3(16,16,4), dim3(32,8), 0, s2>>>(wb, WVO4);
    biasvo_b_k<<<dim3(2,4), 256, 0, s2>>>(bb, wb, BVO4);
    split512b_k<<<dim3(16,16,12), dim3(32,8), 0, s2>>>(wb, WVO4, MH, ML);
    P3 f1; f1.p[0]=enc_ff1; f1.p[1]=enc_ff1 + (size_t)DD*DFF; f1.p[2]=dec_ff1;
    P3 f2; f2.p[0]=enc_ff2; f2.p[1]=enc_ff2 + (size_t)DFF*DD; f2.p[2]=dec_ff2;
    splitffb_k<<<dim3(64,16,3), dim3(32,8), 0, s2>>>(f1, F1H, F1L, DD, DFF);
    splitffb_k<<<dim3(16,64,3), dim3(32,8), 0, s2>>>(f2, F2H, F2L, DFF, DD);
    cudaEventRecord(ev2, s2);

    // stream 0: decoder init + encoder embedding
    decomp_k<<<dim3(1,8,BB), 32>>>(x_enc, SX, TX, CIN, 1, nullptr, nullptr);
    meanenc_k<<<BB*CIN, 256>>>(x_enc, MENC);
    decinit_k<<<(BL7+255)/256, 256>>>(SX, TX, MENC, SEAS, TRD);
    embed_k<<<dim3(2, LL/8, BB), 256>>>(x_enc, x_mark_enc, W_enc_tok, W_enc_tem, A_, S1H, S1L);

    cudaStreamWaitEvent(0, ev2, 0);   // join: weights ready

    // ---- encoder ----
    for (int l=0; l<2; l++){
        run_attn(l, A_, S1H, S1L, S1H, S1L,
                 enc_attn_b + (size_t)l*4*DD,
                 B_, V, QT, KT, SP, SPS, WW, DL, MH, ML, BVO4, s2, ev1, ev2);
        decomp_k<<<dim3(2,8,BB), 256>>>(B_, A_, nullptr, DD, 0, S1H, S1L);
        gemm_tc(0, S1H, S1L, F1H + (size_t)l*DD*DFF, F1L + (size_t)l*DD*DFF,
                nullptr, nullptr, nullptr, S2H, S2L, nullptr, DFF, DD, 1);
        gemm_tc(0, S2H, S2L, F2H + (size_t)l*DFF*DD, F2L + (size_t)l*DFF*DD,
                nullptr, A_, B_, nullptr, nullptr, nullptr, DD, DFF, 0);
        decomp_k<<<dim3(2,8,BB), 256>>>(B_, A_, nullptr, DD, 0, S1H, S1L);
    }
    ln_k<<<MROWS, 256>>>(A_, enc_ln_w, enc_ln_b, B_);
    zero_k<<<(BB*DD+255)/256, 256>>>(CM, BB*DD);
    colsum_k<<<dim3(2,8,BB), 256>>>(B_, CM);
    colsub_k<<<(BLD/4)/256, 256>>>(B_, CM, ENC, ECH, ECL);

    // ---- decoder ----
    embed_k<<<dim3(2, LL/8, BB), 256>>>(SEAS, x_mark_dec, W_dec_tok, W_dec_tem, A_, S1H, S1L);
    run_attn(2, A_, S1H, S1L, S1H, S1L, dec_self_b,
             B_, V, QT, KT, SP, SPS, WW, DL, MH, ML, BVO4, s2, ev1, ev2);
    decomp_k<<<dim3(2,8,BB), 256>>>(B_, A_, T123, DD, 1, S1H, S1L);
    run_attn(3, A_, S1H, S1L, ECH, ECL, dec_cross_b,
             B_, V, QT, KT, SP, SPS, WW, DL, MH, ML, BVO4, s2, ev1, ev2);
    decomp_k<<<dim3(2,8,BB), 256>>>(B_, A_, T123, DD, 2, S1H, S1L);
    gemm_tc(0, S1H, S1L, F1H + (size_t)2*DD*DFF, F1L + (size_t)2*DD*DFF,
            nullptr, nullptr, nullptr, S2H, S2L, nullptr, DFF, DD, 1);
    gemm_tc(0, S2H, S2L, F2H + (size_t)2*DFF*DD, F2L + (size_t)2*DFF*DD,
            nullptr, A_, B_, nullptr, nullptr, nullptr, DD, DFF, 0);
    decomp_k<<<dim3(2,8,BB), 256>>>(B_, A_, T123, DD, 2, S1H, S1L);
    trendconv_k<<<(BL7+255)/256, 256>>>(T123, dec_trend_W, TRD);
    ln_k<<<MROWS, 256>>>(A_, dec_ln_w, dec_ln_b, B_);
    zero_k<<<(BB*DD+255)/256, 256>>>(CM, BB*DD);
    colsum_k<<<dim3(2,8,BB), 256>>>(B_, CM);
    colsub_k<<<(BLD/4)/256, 256>>>(B_, CM, A_, nullptr, nullptr);
    final_k<<<(BB*512*CIN+255)/256, 256>>>(A_, proj_W, proj_b, TRD, out);
}

// round 15
// speedup vs baseline: 1.0661x; 1.0592x over previous
#include <cuda_runtime.h>
#include <cuda_bf16.h>
#include <math.h>

// ---------------- constants ----------------
#define BB   32
#define LL   1024
#define DD   512
#define NH   8
#define HE   64
#define DFF  2048
#define CIN  7
#define MK   4
#define MROWS (BB*LL)          // 32768
#define BLD  (BB*LL*DD)        // 16777216
#define BL7  (BB*LL*CIN)       // 229376
#define TOPK 6

typedef __nv_bfloat16 bf16;

// ---------------- device scratch ----------------
__device__ float g_A   [BLD];
__device__ float g_Bf  [BLD];
__device__ float g_v   [BLD];
__device__ float g_enc [BLD];
__device__ float g_t123[BLD];
__device__ float g_qt  [BLD];
__device__ float g_kt  [BLD];
__device__ float2 g_Sp [BB*NH*4*LL];
__device__ float g_cm  [BB*DD];
__device__ float g_w   [BB*8];
__device__ int   g_dly [BB*8];
__device__ float g_sx  [BL7];
__device__ float g_tx  [BL7];
__device__ float g_seas[BL7];
__device__ float g_trd [BL7];
__device__ float g_menc[BB*CIN];
// fused V weights (4 attentions)
__device__ float g_wvo4[4*DD*DD];     // Wv @ Wo
__device__ float g_bvo4[4*DD];        // bv@Wo + bo
// bf16 split buffers
__device__ bf16 g_mh [12*DD*DD];      // splits: Wq^T[0..3], Wk^T[4..7], WVO^T[8..11]
__device__ bf16 g_ml [12*DD*DD];
__device__ bf16 g_f1h[3*DD*DFF];
__device__ bf16 g_f1l[3*DD*DFF];
__device__ bf16 g_f2h[3*DFF*DD];
__device__ bf16 g_f2l[3*DFF*DD];
__device__ bf16 g_s1h[MROWS*DD];
__device__ bf16 g_s1l[MROWS*DD];
__device__ bf16 g_ench[MROWS*DD];
__device__ bf16 g_encl[MROWS*DD];
__device__ bf16 g_s2h[MROWS*DFF];
__device__ bf16 g_s2l[MROWS*DFF];

struct P4 { const float* p[4]; };
struct P3 { const float* p[3]; };

// ---------------- helpers ----------------
__device__ __forceinline__ void bsplit(float x, bf16& h, bf16& l){
    h = __float2bfloat16(x);
    l = __float2bfloat16(x - __bfloat162float(h));
}
__device__ __forceinline__ unsigned su32(const void* p){
    return (unsigned)__cvta_generic_to_shared(p);
}
__device__ __forceinline__ void cpa16(unsigned dst, const void* src){
    asm volatile("cp.async.cg.shared.global [%0], [%1], 16;" :: "r"(dst), "l"(src));
}
__device__ __forceinline__ void cpa_commit(){
    asm volatile("cp.async.commit_group;" ::: "memory");
}
__device__ __forceinline__ void cpa_wait2(){
    asm volatile("cp.async.wait_group 2;" ::: "memory");
}
__device__ __forceinline__ void ldsm4(unsigned* r, unsigned addr){
    asm volatile("ldmatrix.sync.aligned.m8n8.x4.shared.b16 {%0,%1,%2,%3}, [%4];"
        : "=r"(r[0]), "=r"(r[1]), "=r"(r[2]), "=r"(r[3]) : "r"(addr));
}
__device__ __forceinline__ void mma16(float* d, const unsigned* a, unsigned b0, unsigned b1){
    asm volatile("mma.sync.aligned.m16n8k16.row.col.f32.bf16.bf16.f32 "
        "{%0,%1,%2,%3},{%4,%5,%6,%7},{%8,%9},{%0,%1,%2,%3};"
        : "+f"(d[0]), "+f"(d[1]), "+f"(d[2]), "+f"(d[3])
        : "r"(a[0]), "r"(a[1]), "r"(a[2]), "r"(a[3]), "r"(b0), "r"(b1));
}

// ---------------- split-bf16 mma.sync GEMM (4-stage ring, single sync/iter) ----------------
#define RSTRIDE 80
#define AREA    10240
#define STAGEB  40960
#define NSTAGE  4
#define GEMM_SMEM (NSTAGE*STAGEB)   // 163840
__global__ void __launch_bounds__(512,1) gemm_mma_k(
    const bf16* __restrict__ Ahp, const bf16* __restrict__ Alp,
    const bf16* __restrict__ Bhp, const bf16* __restrict__ Blp,
    const float* __restrict__ bias, const float* __restrict__ res,
    float* __restrict__ C, bf16* __restrict__ Ch, bf16* __restrict__ Cl,
    float* __restrict__ Ct,
    int N, int K, int dogelu)
{
    extern __shared__ __align__(16) char dsm[];
    const int tid = threadIdx.x;
    const int lane = tid & 31, warp = tid >> 5;
    const int wm = warp >> 2, wn = warp & 3;
    const int bx = blockIdx.x, by = blockIdx.y;
    const int S = K >> 5;
    const unsigned sbase = su32(dsm);

    const int lrow = tid >> 2, lc16 = tid & 3;
    const bf16* gA_h = Ahp + (size_t)(by*128 + lrow)*K;
    const bf16* gA_l = Alp + (size_t)(by*128 + lrow)*K;
    const bf16* gB_h = Bhp + (size_t)(bx*128 + lrow)*K;
    const bf16* gB_l = Blp + (size_t)(bx*128 + lrow)*K;
    const unsigned sdst = lrow*RSTRIDE + lc16*16;

    float acc[2][4][4];
#pragma unroll
    for (int i=0;i<2;i++)
#pragma unroll
        for (int j=0;j<4;j++)
#pragma unroll
            for (int t=0;t<4;t++) acc[i][j][t]=0.f;

#pragma unroll
    for (int p=0;p<3;p++){
        if (p < S){
            unsigned b = sbase + p*STAGEB + sdst;
            int gk = p*32 + lc16*8;
            cpa16(b,            gA_h + gk);
            cpa16(b + AREA,     gA_l + gk);
            cpa16(b + 2*AREA,   gB_h + gk);
            cpa16(b + 3*AREA,   gB_l + gk);
        }
        cpa_commit();
    }

    const unsigned arow = (wm*32 + (lane & 15))*RSTRIDE + (lane >> 4)*16;
    const unsigned brow = (wn*32 + (lane & 15))*RSTRIDE + (lane >> 4)*16;

    for (int s=0; s<S; s++){
        cpa_wait2();
        __syncthreads();
        // prefetch s+3 into buf (s+3)%4 == (s-1)%4 — reads of that buffer are
        // ordered before this sync, so no trailing barrier is needed.
        if (s+3 < S){
            unsigned b = sbase + ((s+3) & 3)*STAGEB + sdst;
            int gk = (s+3)*32 + lc16*8;
            cpa16(b,            gA_h + gk);
            cpa16(b + AREA,     gA_l + gk);
            cpa16(b + 2*AREA,   gB_h + gk);
            cpa16(b + 3*AREA,   gB_l + gk);
        }
        cpa_commit();
        const unsigned sb = sbase + (s & 3)*STAGEB;
#pragma unroll
        for (int k16=0; k16<2; k16++){
            const unsigned ko = k16*32;
            unsigned ah[8], al[8], bh[8], bl[8];
            ldsm4(ah,   sb + arow + ko);
            ldsm4(ah+4, sb + arow + ko + 16*RSTRIDE);
            ldsm4(al,   sb + AREA + arow + ko);
            ldsm4(al+4, sb + AREA + arow + ko + 16*RSTRIDE);
            ldsm4(bh,   sb + 2*AREA + brow + ko);
            ldsm4(bh+4, sb + 2*AREA + brow + ko + 16*RSTRIDE);
            ldsm4(bl,   sb + 3*AREA + brow + ko);
            ldsm4(bl+4, sb + 3*AREA + brow + ko + 16*RSTRIDE);
#pragma unroll
            for (int mf=0; mf<2; mf++){
#pragma unroll
                for (int nf=0; nf<4; nf++){
                    int g = (nf>>1)*4 + (nf&1);
                    mma16(acc[mf][nf], ah+mf*4, bh[g], bh[g+2]);
                    mma16(acc[mf][nf], ah+mf*4, bl[g], bl[g+2]);
                    mma16(acc[mf][nf], al+mf*4, bh[g], bh[g+2]);
                }
            }
        }
    }
    __syncthreads();

    if (Ct){
        float* st = (float*)dsm;  // [128 cols][129]
#pragma unroll
        for (int mf=0; mf<2; mf++){
#pragma unroll
            for (int nf=0; nf<4; nf++){
                int rl = wm*32 + mf*16 + (lane>>2);
                int cl = wn*32 + nf*8 + ((lane&3)<<1);
                float* d = acc[mf][nf];
#pragma unroll
                for (int h=0; h<2; h++){
                    float b0 = bias ? __ldg(&bias[bx*128 + cl])   : 0.f;
                    float b1 = bias ? __ldg(&bias[bx*128 + cl+1]) : 0.f;
                    st[cl*129 + rl + 8*h]     = d[2*h]   + b0;
                    st[(cl+1)*129 + rl + 8*h] = d[2*h+1] + b1;
                }
            }
        }
        __syncthreads();
        int gr = by*128;
        int b  = gr >> 10;
        int l0 = gr & 1023;
#pragma unroll
        for (int cc=0; cc<8; cc++){
            int col = warp*8 + cc;
            size_t rowoff = ((size_t)b*DD + bx*128 + col)*LL + l0;
#pragma unroll
            for (int i=0;i<4;i++){
                int r = lane + i*32;
                Ct[rowoff + r] = st[col*129 + r];
            }
        }
        return;
    }

#pragma unroll
    for (int mf=0; mf<2; mf++){
#pragma unroll
        for (int nf=0; nf<4; nf++){
            int r0  = by*128 + wm*32 + mf*16 + (lane>>2);
            int col = bx*128 + wn*32 + nf*8 + ((lane&3)<<1);
            float* d = acc[mf][nf];
#pragma unroll
            for (int h=0; h<2; h++){
                int r = r0 + h*8;
                size_t rowoff = (size_t)r * N;
                float2 o = make_float2(d[2*h], d[2*h+1]);
                if (bias){ o.x += __ldg(&bias[col]); o.y += __ldg(&bias[col+1]); }
                if (dogelu){
                    o.x = 0.5f*o.x*(1.0f+erff(o.x*0.7071067811865476f));
                    o.y = 0.5f*o.y*(1.0f+erff(o.y*0.7071067811865476f));
                }
                if (res){
                    float2 rr = *(const float2*)&res[rowoff + col];
                    o.x += rr.x; o.y += rr.y;
                }
                if (Ch){
                    bf16 h0,l0,h1,l1;
                    bsplit(o.x,h0,l0); bsplit(o.y,h1,l1);
                    __nv_bfloat162 hv; hv.x=h0; hv.y=h1;
                    __nv_bfloat162 lv; lv.x=l0; lv.y=l1;
                    *(__nv_bfloat162*)&Ch[rowoff + col] = hv;
                    *(__nv_bfloat162*)&Cl[rowoff + col] = lv;
                } else {
                    *(float2*)&C[rowoff + col] = o;
                }
            }
        }
    }
}

// ---------------- batched 512x512 matmuls: WVO[z] = Wv @ Wo ----------------
__global__ void mmvo_b_k(P4 wb, float* __restrict__ wvo){
    __shared__ float As[32][33], Bs[32][33];
    int z = blockIdx.z;
    const float* A = wb.p[z] + (size_t)2*DD*DD;
    const float* B = wb.p[z] + (size_t)3*DD*DD;
    float* C = wvo + (size_t)z*DD*DD;
    int i0 = blockIdx.y*32, j0 = blockIdx.x*32;
    int tx = threadIdx.x, ty = threadIdx.y;
    float acc[4] = {0.f,0.f,0.f,0.f};
    for (int k0=0;k0<512;k0+=32){
        for (int r=ty;r<32;r+=8){
            As[r][tx] = A[(size_t)(i0+r)*512 + k0+tx];
            Bs[r][tx] = B[(size_t)(k0+r)*512 + j0+tx];
        }
        __syncthreads();
#pragma unroll
        for (int k=0;k<32;k++){
            float bv = Bs[k][tx];
#pragma unroll
            for (int u=0;u<4;u++) acc[u] += As[ty+8*u][k]*bv;
        }
        __syncthreads();
    }
#pragma unroll
    for (int u=0;u<4;u++) C[(size_t)(i0+ty+8*u)*512 + j0+tx] = acc[u];
}

// ---------------- batched fused bias: bvo[z] = bv@Wo + bo ----------------
__global__ void biasvo_b_k(P4 bb, P4 wb, float* __restrict__ bvo){
    int z = blockIdx.y;
    int j = blockIdx.x*256 + threadIdx.x;
    if (j >= 512) return;
    const float* bv = bb.p[z] + 2*DD;
    const float* bo = bb.p[z] + 3*DD;
    const float* Wo = wb.p[z] + (size_t)3*DD*DD;
    float s = bo[j];
    for (int m=0;m<512;m++) s += bv[m]*Wo[(size_t)m*512 + j];
    bvo[z*DD + j] = s;
}

// ---------------- batched split+transpose of 12 512x512 mats ----------------
__global__ void split512b_k(P4 wb, const float* __restrict__ wvo,
                            bf16* __restrict__ oh, bf16* __restrict__ ol){
    __shared__ float t[32][33];
    int z = blockIdx.z;
    const float* W;
    if (z < 4)       W = wb.p[z];
    else if (z < 8)  W = wb.p[z-4] + (size_t)DD*DD;
    else             W = wvo + (size_t)(z-8)*DD*DD;
    bf16* ohp = oh + (size_t)z*DD*DD;
    bf16* olp = ol + (size_t)z*DD*DD;
    int n0 = blockIdx.x*32, k0 = blockIdx.y*32;
    int x = threadIdx.x, y = threadIdx.y;
    for (int i=y;i<32;i+=8)
        t[i][x] = W[(size_t)(k0+i)*DD + n0 + x];
    __syncthreads();
    for (int i=y;i<32;i+=8){
        float v = t[x][i];
        bf16 h,l; bsplit(v,h,l);
        ohp[(size_t)(n0+i)*DD + k0 + x] = h;
        olp[(size_t)(n0+i)*DD + k0 + x] = l;
    }
}

// ---------------- batched split+transpose for FF weights ----------------
__global__ void splitffb_k(P3 Wl, bf16* __restrict__ oh, bf16* __restrict__ ol,
                           int Kd, int Nd){
    __shared__ float t[32][33];
    int z = blockIdx.z;
    const float* W = Wl.p[z];
    bf16* ohp = oh + (size_t)z*Kd*Nd;
    bf16* olp = ol + (size_t)z*Kd*Nd;
    int n0 = blockIdx.x*32, k0 = blockIdx.y*32;
    int x = threadIdx.x, y = threadIdx.y;
    for (int i=y;i<32;i+=8)
        t[i][x] = W[(size_t)(k0+i)*Nd + n0 + x];
    __syncthreads();
    for (int i=y;i<32;i+=8){
        float v = t[x][i];
        bf16 h,l; bsplit(v,h,l);
        ohp[(size_t)(n0+i)*Kd + k0 + x] = h;
        olp[(size_t)(n0+i)*Kd + k0 + x] = l;
    }
}

// ---------------- FFT helpers ----------------
__device__ __forceinline__ float2 cmul(float2 a, float2 b){
    return make_float2(a.x*b.x - a.y*b.y, a.x*b.y + a.y*b.x);
}
__device__ __forceinline__ int dig4rev(int t){
    int br = __brev(t) >> 22;
    return ((br >> 1) & 0x155) | ((br << 1) & 0x2AA);
}
__device__ void fft1024_r4(float2* z, const float2* tw, int tid, int inv){
    const float s4 = inv ? 1.0f : -1.0f;
#pragma unroll
    for (int s=0; s<5; s++){
        __syncthreads();
        const int quarter = 1 << (2*s);
        const int pos = tid & (quarter-1);
        const int g   = tid >> (2*s);
        const int base = (g << (2*s+2)) + pos;
        const int tstep = pos << (8 - 2*s);
        float2 x0 = z[base];
        float2 x1 = cmul(tw[tstep],   z[base + quarter]);
        float2 x2 = cmul(tw[2*tstep], z[base + 2*quarter]);
        float2 x3 = cmul(tw[3*tstep], z[base + 3*quarter]);
        float2 t0 = make_float2(x0.x+x2.x, x0.y+x2.y);
        float2 t1 = make_float2(x0.x-x2.x, x0.y-x2.y);
        float2 t2 = make_float2(x1.x+x3.x, x1.y+x3.y);
        float2 t3 = make_float2(x1.x-x3.x, x1.y-x3.y);
        float2 rot = make_float2(-s4*t3.y, s4*t3.x);
        z[base]             = make_float2(t0.x+t2.x, t0.y+t2.y);
        z[base+quarter]     = make_float2(t1.x+rot.x, t1.y+rot.y);
        z[base+2*quarter]   = make_float2(t0.x-t2.x, t0.y-t2.y);
        z[base+3*quarter]   = make_float2(t1.x-rot.x, t1.y-rot.y);
    }
    __syncthreads();
}

#define EPB 16
__global__ void corr_fwd_k(const float* __restrict__ qt, const float* __restrict__ kt,
                           float2* __restrict__ Sp){
    __shared__ float2 z[1024];
    __shared__ float2 acc[1024];
    __shared__ float2 tw[1024];
    int bh = blockIdx.x;
    int chunk = blockIdx.y;
    int tid = threadIdx.x;
    for (int j=tid;j<1024;j+=256){
        float s,c; sincosf((float)j * (6.283185307179586f/1024.0f), &s, &c);
        tw[j] = make_float2(c, -s);
    }
    for (int f=tid;f<1024;f+=256) acc[f] = make_float2(0.f,0.f);
    for (int ei=0; ei<EPB; ei++){
        int e = chunk*EPB + ei;
        const float* qp = qt + ((size_t)bh*HE + e)*LL;
        const float* kp = kt + ((size_t)bh*HE + e)*LL;
        __syncthreads();
        for (int t=tid;t<1024;t+=256){
            z[dig4rev(t)] = make_float2(qp[t], kp[t]);
        }
        fft1024_r4(z, tw, tid, 0);
        for (int f=tid;f<1024;f+=256){
            float2 Zf = z[f];
            float2 Zm = z[(1024 - f) & 1023];
            float2 Zc = make_float2(Zm.x, -Zm.y);
            float2 Q  = make_float2(0.5f*(Zf.x+Zc.x), 0.5f*(Zf.y+Zc.y));
            float dx = Zf.x - Zc.x, dy = Zf.y - Zc.y;
            float2 Kk = make_float2(0.5f*dy, -0.5f*dx);
            acc[f].x += Q.x*Kk.x + Q.y*Kk.y;
            acc[f].y += Q.y*Kk.x - Q.x*Kk.y;
        }
    }
    __syncthreads();
    float2* dst = Sp + ((size_t)bh*4 + chunk)*LL;
    for (int f=tid;f<1024;f+=256) dst[f] = acc[f];
}

__global__ void corr_topk_k(const float2* __restrict__ Sp, float* __restrict__ wout,
                            int* __restrict__ dout){
    __shared__ float2 z[1024];
    __shared__ float2 tw[1024];
    __shared__ float corr[1024];
    __shared__ float rv[256];
    __shared__ int   ri[256];
    __shared__ float wv[TOPK];
    __shared__ int   dv[TOPK];
    int b = blockIdx.x, tid = threadIdx.x;
    for (int j=tid;j<1024;j+=256){
        float s,c; sincosf((float)j * (6.283185307179586f/1024.0f), &s, &c);
        tw[j] = make_float2(c, s);   // inverse
    }
    for (int f=tid;f<1024;f+=256){
        float sx=0.f, sy=0.f;
        const float2* sp = Sp + (size_t)b*32*LL + f;
#pragma unroll
        for (int sl=0;sl<32;sl++){
            float2 v = sp[(size_t)sl*LL];
            sx += v.x; sy += v.y;
        }
        z[dig4rev(f)] = make_float2(sx, sy);
    }
    fft1024_r4(z, tw, tid, 1);
    const float scale = 1.0f / (1024.0f * 512.0f);
    for (int f=tid;f<1024;f+=256) corr[f] = z[f].x * scale;
    __syncthreads();
    for (int it=0; it<TOPK; it++){
        float best = -1e30f; int bi = 1<<30;
        for (int f=tid;f<1024;f+=256){
            float v = corr[f];
            if (v > best || (v == best && f < bi)){ best = v; bi = f; }
        }
        rv[tid]=best; ri[tid]=bi; __syncthreads();
        for (int off=128; off; off>>=1){
            if (tid < off){
                if (rv[tid+off] > rv[tid] || (rv[tid+off]==rv[tid] && ri[tid+off]<ri[tid])){
                    rv[tid]=rv[tid+off]; ri[tid]=ri[tid+off];
                }
            }
            __syncthreads();
        }
        if (tid==0){ wv[it]=rv[0]; dv[it]=ri[0]; corr[ri[0]] = -1e30f; }
        __syncthreads();
    }
    if (tid==0){
        float mx = wv[0];
        float ex[TOPK]; float s=0.f;
        for (int i=0;i<TOPK;i++){ ex[i]=expf(wv[i]-mx); s+=ex[i]; }
        for (int i=0;i<TOPK;i++){ wout[b*8+i]=ex[i]/s; dout[b*8+i]=dv[i]; }
    }
}

// ---------------- roll & weight + residual (float4) ----------------
__global__ void roll_res_k(const float* __restrict__ P, const float* __restrict__ w,
                           const int* __restrict__ d, const float* __restrict__ res,
                           float* __restrict__ out){
    int idx = blockIdx.x*256 + threadIdx.x;
    if (idx >= BLD/4) return;
    int c4 = idx & 127;
    int t = (idx >> 7) & (LL-1);
    int b = idx >> 17;
    float4 s = __ldg(&((const float4*)res)[idx]);
#pragma unroll
    for (int i=0;i<TOPK;i++){
        int   dl = __ldg(&d[b*8+i]);
        float wi = __ldg(&w[b*8+i]);
        int tt = (t + dl) & (LL-1);
        float4 v = __ldg(&((const float4*)P)[((size_t)(b*LL + tt) << 7) + c4]);
        s.x += wi*v.x; s.y += wi*v.y; s.z += wi*v.z; s.w += wi*v.w;
    }
    ((float4*)out)[idx] = s;
}

// ---------------- series decomposition (moving mean k=25) ----------------
__global__ void decomp_k(const float* __restrict__ x, float* __restrict__ seas,
                         float* __restrict__ trend, int C, int mode,
                         bf16* __restrict__ oh, bf16* __restrict__ ol){
    int b = blockIdx.z;
    int c = blockIdx.x*blockDim.x + threadIdx.x;
    if (c >= C) return;
    int l0 = blockIdx.y * 128;
    const float* xb = x + (size_t)b*LL*C + c;
    float sum = 0.f;
    for (int j=l0-12;j<=l0+12;j++){
        int jj = min(max(j,0), LL-1);
        sum += xb[(size_t)jj*C];
    }
    for (int l=l0; l<l0+128; l++){
        float m = sum * (1.0f/25.0f);
        size_t o = (size_t)b*LL*C + (size_t)l*C + c;
        float sv = x[o] - m;
        seas[o] = sv;
        if (oh){ bf16 h,lo; bsplit(sv,h,lo); oh[o]=h; ol[o]=lo; }
        if (mode==1) trend[o] = m;
        else if (mode==2) trend[o] += m;
        int ja = min(l+13, LL-1), jr = max(l-12, 0);
        sum += xb[(size_t)ja*C] - xb[(size_t)jr*C];
    }
}

// ---------------- layernorm over feature dim ----------------
__global__ void ln_k(const float* __restrict__ x, const float* __restrict__ w,
                     const float* __restrict__ bv, float* __restrict__ y){
    __shared__ float red[256];
    int row = blockIdx.x, tid = threadIdx.x;
    const float* xr = x + (size_t)row*DD;
    float v0 = xr[tid], v1 = xr[tid+256];
    red[tid] = v0+v1; __syncthreads();
    for (int o=128;o;o>>=1){ if (tid<o) red[tid]+=red[tid+o]; __syncthreads(); }
    float mu = red[0]*(1.0f/512.0f);
    __syncthreads();
    float d0=v0-mu, d1=v1-mu;
    red[tid] = d0*d0+d1*d1; __syncthreads();
    for (int o=128;o;o>>=1){ if (tid<o) red[tid]+=red[tid+o]; __syncthreads(); }
    float rstd = rsqrtf(red[0]*(1.0f/512.0f) + 1e-5f);
    y[(size_t)row*DD + tid]     = d0*rstd*w[tid]     + bv[tid];
    y[(size_t)row*DD + tid+256] = d1*rstd*w[tid+256] + bv[tid+256];
}

// ---------------- column (time) mean ----------------
__global__ void zero_k(float* p, int n){
    int i = blockIdx.x*blockDim.x + threadIdx.x;
    if (i < n) p[i] = 0.0f;
}
__global__ void colsum_k(const float* __restrict__ x, float* __restrict__ cm){
    int b = blockIdx.z;
    int c = blockIdx.x*256 + threadIdx.x;
    int l0 = blockIdx.y*128;
    float s=0.f;
    for (int l=l0;l<l0+128;l++) s += x[((size_t)b*LL + l)*DD + c];
    atomicAdd(&cm[b*DD + c], s);
}
__global__ void colsub_k(const float* __restrict__ x, const float* __restrict__ cm,
                         float* __restrict__ y, bf16* __restrict__ oh, bf16* __restrict__ ol){
    int idx = blockIdx.x*256 + threadIdx.x;
    if (idx >= BLD/4) return;
    int c4 = idx & 127;
    int b = idx >> 17;
    float4 xv = __ldg(&((const float4*)x)[idx]);
    float4 cv = __ldg(&((const float4*)cm)[b*128 + c4]);
    float4 v;
    v.x = xv.x - cv.x*(1.0f/1024.0f);
    v.y = xv.y - cv.y*(1.0f/1024.0f);
    v.z = xv.z - cv.z*(1.0f/1024.0f);
    v.w = xv.w - cv.w*(1.0f/1024.0f);
    ((float4*)y)[idx] = v;
    if (oh){
        bf16 h0,l0,h1,l1,h2,l2,h3,l3;
        bsplit(v.x,h0,l0); bsplit(v.y,h1,l1); bsplit(v.z,h2,l2); bsplit(v.w,h3,l3);
        __nv_bfloat162* oh2 = (__nv_bfloat162*)oh;
        __nv_bfloat162* ol2 = (__nv_bfloat162*)ol;
        __nv_bfloat162 a,bb2;
        a.x=h0; a.y=h1; bb2.x=h2; bb2.y=h3;
        oh2[2*idx]=a; oh2[2*idx+1]=bb2;
        a.x=l0; a.y=l1; bb2.x=l2; bb2.y=l3;
        ol2[2*idx]=a; ol2[2*idx+1]=bb2;
    }
}

// ---------------- embedding (weight-register reuse, 8 l per thread) ----------------
__global__ void embed_k(const float* __restrict__ x, const float* __restrict__ mark,
                        const float* __restrict__ Wtok, const float* __restrict__ Wtem,
                        float* __restrict__ out, bf16* __restrict__ oh, bf16* __restrict__ ol){
    int d = blockIdx.x*256 + threadIdx.x;
    int b = blockIdx.z;
    int l0 = blockIdx.y*8;
    float w[21], wt[4];
#pragma unroll
    for (int i=0;i<21;i++) w[i] = __ldg(&Wtok[(size_t)i*DD + d]);
#pragma unroll
    for (int m=0;m<MK;m++) wt[m] = __ldg(&Wtem[(size_t)m*DD + d]);
#pragma unroll
    for (int i=0;i<8;i++){
        int l = l0 + i;
        int lm = (l + LL - 1) & (LL-1), lp = (l + 1) & (LL-1);
        const float* x0 = x + ((size_t)b*LL + lm)*CIN;
        const float* x1 = x + ((size_t)b*LL + l )*CIN;
        const float* x2 = x + ((size_t)b*LL + lp)*CIN;
        float s = 0.f;
#pragma unroll
        for (int c=0;c<CIN;c++){
            s += x0[c]*w[c];
            s += x1[c]*w[7+c];
            s += x2[c]*w[14+c];
        }
        const float* mk = mark + ((size_t)b*LL + l)*MK;
#pragma unroll
        for (int m=0;m<MK;m++) s += mk[m]*wt[m];
        size_t o = ((size_t)b*LL + l)*DD + d;
        out[o] = s;
        bf16 h,lo; bsplit(s,h,lo); oh[o]=h; ol[o]=lo;
    }
}

// ---------------- mean of x_enc over time ----------------
__global__ void meanenc_k(const float* __restrict__ x, float* __restrict__ m){
    __shared__ float red[256];
    int b = blockIdx.x / CIN, c = blockIdx.x % CIN;
    int tid = threadIdx.x;
    float s=0.f;
    for (int l=tid;l<LL;l+=256) s += x[((size_t)b*LL + l)*CIN + c];
    red[tid]=s; __syncthreads();
    for (int o=128;o;o>>=1){ if (tid<o) red[tid]+=red[tid+o]; __syncthreads(); }
    if (tid==0) m[blockIdx.x] = red[0]*(1.0f/1024.0f);
}

__global__ void decinit_k(const float* __restrict__ sx, const float* __restrict__ tx,
                          const float* __restrict__ menc, float* __restrict__ seas,
                          float* __restrict__ trend){
    int idx = blockIdx.x*256 + threadIdx.x;
    if (idx >= BL7) return;
    int c = idx % CIN;
    int l = (idx / CIN) % LL;
    int b = idx / (CIN*LL);
    if (l < 512){
        size_t src = ((size_t)b*LL + 512 + l)*CIN + c;
        seas[idx]  = sx[src];
        trend[idx] = tx[src];
    } else {
        seas[idx]  = 0.f;
        trend[idx] = menc[b*CIN + c];
    }
}

__global__ void trendconv_k(const float* __restrict__ t123, const float* __restrict__ Wt,
                            float* __restrict__ trend){
    int idx = blockIdx.x*256 + threadIdx.x;
    if (idx >= BL7) return;
    int c = idx % CIN;
    int l = (idx / CIN) % LL;
    int b = idx / (CIN*LL);
    int lm = (l + LL - 1) & (LL-1), lp = (l + 1) & (LL-1);
    const float* r0 = t123 + ((size_t)b*LL + lm)*DD;
    const float* r1 = t123 + ((size_t)b*LL + l )*DD;
    const float* r2 = t123 + ((size_t)b*LL + lp)*DD;
    float s = 0.f;
    for (int d=0; d<DD; d++){
        s += r0[d]*__ldg(&Wt[(0*DD+d)*CIN + c]);
        s += r1[d]*__ldg(&Wt[(1*DD+d)*CIN + c]);
        s += r2[d]*__ldg(&Wt[(2*DD+d)*CIN + c]);
    }
    trend[idx] += s;
}

__global__ void final_k(const float* __restrict__ dec, const float* __restrict__ projW,
                        const float* __restrict__ projb, const float* __restrict__ trend,
                        float* __restrict__ out){
    int idx = blockIdx.x*256 + threadIdx.x;
    if (idx >= BB*512*CIN) return;
    int c = idx % CIN;
    int lp = (idx / CIN) % 512;
    int b = idx / (512*CIN);
    int l = 512 + lp;
    const float* r = dec + ((size_t)b*LL + l)*DD;
    float s = projb[c];
    for (int d=0; d<DD; d++) s += r[d]*__ldg(&projW[d*CIN + c]);
    out[idx] = trend[((size_t)b*LL + l)*CIN + c] + s;
}

// ---------------- host orchestration ----------------
static void gemm_tc(const bf16* ah, const bf16* al, const bf16* bh, const bf16* bl,
                    const float* bias, const float* res,
                    float* C, bf16* Ch, bf16* Cl, float* Ct, int N, int K, int gelu){
    dim3 g(N/128, MROWS/128);
    gemm_mma_k<<<g, 512, GEMM_SMEM>>>(ah, al, bh, bl, bias, res, C, Ch, Cl, Ct, N, K, gelu);
}

static void run_attn(int ai, const float* res,
                     const bf16* xqh, const bf16* xql,
                     const bf16* xkvh, const bf16* xkvl,
                     const float* bias, float* outb, float* Pv,
                     float* qt, float* kt, float2* Sp, float* wbuf, int* dbuf,
                     bf16* MH, bf16* ML, float* BVO4){
    gemm_tc(xqh, xql,  MH + (size_t)ai*DD*DD,     ML + (size_t)ai*DD*DD,
            bias,      nullptr, nullptr, nullptr, nullptr, qt, DD, DD, 0);
    gemm_tc(xkvh, xkvl, MH + (size_t)(4+ai)*DD*DD, ML + (size_t)(4+ai)*DD*DD,
            bias + DD, nullptr, nullptr, nullptr, nullptr, kt, DD, DD, 0);
    gemm_tc(xkvh, xkvl, MH + (size_t)(8+ai)*DD*DD, ML + (size_t)(8+ai)*DD*DD,
            BVO4 + ai*DD, nullptr, Pv, nullptr, nullptr, nullptr, DD, DD, 0);
    corr_fwd_k<<<dim3(BB*NH, 4), 256>>>(qt, kt, Sp);
    corr_topk_k<<<BB, 256>>>(Sp, wbuf, dbuf);
    roll_res_k<<<(BLD/4)/256, 256>>>(Pv, wbuf, dbuf, res, outb);
}

extern "C" void kernel_launch(void* const* d_in, const int* in_sizes, int n_in,
                              void* d_out, int out_size){
    const float* x_enc      = (const float*)d_in[0];
    const float* x_mark_enc = (const float*)d_in[1];
    const float* x_mark_dec = (const float*)d_in[3];
    const float* W_enc_tok  = (const float*)d_in[4];
    const float* W_enc_tem  = (const float*)d_in[5];
    const float* W_dec_tok  = (const float*)d_in[6];
    const float* W_dec_tem  = (const float*)d_in[7];
    const float* enc_attn_W = (const float*)d_in[8];
    const float* enc_attn_b = (const float*)d_in[9];
    const float* enc_ff1    = (const float*)d_in[10];
    const float* enc_ff2    = (const float*)d_in[11];
    const float* enc_ln_w   = (const float*)d_in[12];
    const float* enc_ln_b   = (const float*)d_in[13];
    const float* dec_self_W = (const float*)d_in[14];
    const float* dec_self_b = (const float*)d_in[15];
    const float* dec_cross_W= (const float*)d_in[16];
    const float* dec_cross_b= (const float*)d_in[17];
    const float* dec_ff1    = (const float*)d_in[18];
    const float* dec_ff2    = (const float*)d_in[19];
    const float* dec_trend_W= (const float*)d_in[20];
    const float* dec_ln_w   = (const float*)d_in[21];
    const float* dec_ln_b   = (const float*)d_in[22];
    const float* proj_W     = (const float*)d_in[23];
    const float* proj_b     = (const float*)d_in[24];
    float* out = (float*)d_out;

    cudaFuncSetAttribute(gemm_mma_k, cudaFuncAttributeMaxDynamicSharedMemorySize, GEMM_SMEM);

    void *pA,*pB,*pv,*penc,*pt123,*pqt,*pkt,*pSp,*pcm,*pw,*pd;
    void *psx,*ptx,*pseas,*ptrd,*pmenc,*pwvo,*pbvo;
    void *ps1h,*ps1l,*pech,*pecl,*ps2h,*ps2l;
    void *pmh,*pml,*pf1h,*pf1l,*pf2h,*pf2l;
    cudaGetSymbolAddress(&pA, g_A);       cudaGetSymbolAddress(&pB, g_Bf);
    cudaGetSymbolAddress(&pv, g_v);       cudaGetSymbolAddress(&penc, g_enc);
    cudaGetSymbolAddress(&pt123, g_t123);
    cudaGetSymbolAddress(&pqt, g_qt);     cudaGetSymbolAddress(&pkt, g_kt);
    cudaGetSymbolAddress(&pSp, g_Sp);     cudaGetSymbolAddress(&pcm, g_cm);
    cudaGetSymbolAddress(&pw, g_w);       cudaGetSymbolAddress(&pd, g_dly);
    cudaGetSymbolAddress(&psx, g_sx);     cudaGetSymbolAddress(&ptx, g_tx);
    cudaGetSymbolAddress(&pseas, g_seas); cudaGetSymbolAddress(&ptrd, g_trd);
    cudaGetSymbolAddress(&pmenc, g_menc);
    cudaGetSymbolAddress(&pwvo, g_wvo4);  cudaGetSymbolAddress(&pbvo, g_bvo4);
    cudaGetSymbolAddress(&ps1h, g_s1h);   cudaGetSymbolAddress(&ps1l, g_s1l);
    cudaGetSymbolAddress(&pech, g_ench);  cudaGetSymbolAddress(&pecl, g_encl);
    cudaGetSymbolAddress(&ps2h, g_s2h);   cudaGetSymbolAddress(&ps2l, g_s2l);
    cudaGetSymbolAddress(&pmh, g_mh);     cudaGetSymbolAddress(&pml, g_ml);
    cudaGetSymbolAddress(&pf1h, g_f1h);   cudaGetSymbolAddress(&pf1l, g_f1l);
    cudaGetSymbolAddress(&pf2h, g_f2h);   cudaGetSymbolAddress(&pf2l, g_f2l);

    float *A_=(float*)pA, *B_=(float*)pB, *V=(float*)pv;
    float *ENC=(float*)penc, *T123=(float*)pt123, *QT=(float*)pqt, *KT=(float*)pkt;
    float2 *SP=(float2*)pSp;
    float *CM=(float*)pcm, *WW=(float*)pw; int *DL=(int*)pd;
    float *SX=(float*)psx, *TX=(float*)ptx, *SEAS=(float*)pseas, *TRD=(float*)ptrd, *MENC=(float*)pmenc;
    float *WVO4=(float*)pwvo, *BVO4=(float*)pbvo;
    bf16 *S1H=(bf16*)ps1h, *S1L=(bf16*)ps1l, *ECH=(bf16*)pech, *ECL=(bf16*)pecl;
    bf16 *S2H=(bf16*)ps2h, *S2L=(bf16*)ps2l;
    bf16 *MH=(bf16*)pmh, *ML=(bf16*)pml;
    bf16 *F1H=(bf16*)pf1h, *F1L=(bf16*)pf1l, *F2H=(bf16*)pf2h, *F2L=(bf16*)pf2l;

    // ---- batched weight prep ----
    P4 wb; wb.p[0]=enc_attn_W; wb.p[1]=enc_attn_W + (size_t)4*DD*DD;
           wb.p[2]=dec_self_W; wb.p[3]=dec_cross_W;
    P4 bb; bb.p[0]=enc_attn_b; bb.p[1]=enc_attn_b + 4*DD;
           bb.p[2]=dec_self_b; bb.p[3]=dec_cross_b;
    mmvo_b_k<<<dim3(16,16,4), dim3(32,8)>>>(wb, WVO4);
    biasvo_b_k<<<dim3(2,4), 256>>>(bb, wb, BVO4);
    split512b_k<<<dim3(16,16,12), dim3(32,8)>>>(wb, WVO4, MH, ML);
    P3 f1; f1.p[0]=enc_ff1; f1.p[1]=enc_ff1 + (size_t)DD*DFF; f1.p[2]=dec_ff1;
    P3 f2; f2.p[0]=enc_ff2; f2.p[1]=enc_ff2 + (size_t)DFF*DD; f2.p[2]=dec_ff2;
    splitffb_k<<<dim3(64,16,3), dim3(32,8)>>>(f1, F1H, F1L, DD, DFF);
    splitffb_k<<<dim3(16,64,3), dim3(32,8)>>>(f2, F2H, F2L, DFF, DD);

    // ---- decoder init tensors (from x_enc) ----
    decomp_k<<<dim3(1,8,BB), 32>>>(x_enc, SX, TX, CIN, 1, nullptr, nullptr);
    meanenc_k<<<BB*CIN, 256>>>(x_enc, MENC);
    decinit_k<<<(BL7+255)/256, 256>>>(SX, TX, MENC, SEAS, TRD);

    // ---- encoder ----
    embed_k<<<dim3(2, LL/8, BB), 256>>>(x_enc, x_mark_enc, W_enc_tok, W_enc_tem, A_, S1H, S1L);
    for (int l=0; l<2; l++){
        run_attn(l, A_, S1H, S1L, S1H, S1L,
                 enc_attn_b + (size_t)l*4*DD,
                 B_, V, QT, KT, SP, WW, DL, MH, ML, BVO4);
        decomp_k<<<dim3(2,8,BB), 256>>>(B_, A_, nullptr, DD, 0, S1H, S1L);
        gemm_tc(S1H, S1L, F1H + (size_t)l*DD*DFF, F1L + (size_t)l*DD*DFF,
                nullptr, nullptr, nullptr, S2H, S2L, nullptr, DFF, DD, 1);
        gemm_tc(S2H, S2L, F2H + (size_t)l*DFF*DD, F2L + (size_t)l*DFF*DD,
                nullptr, A_, B_, nullptr, nullptr, nullptr, DD, DFF, 0);
        decomp_k<<<dim3(2,8,BB), 256>>>(B_, A_, nullptr, DD, 0, S1H, S1L);
    }
    ln_k<<<MROWS, 256>>>(A_, enc_ln_w, enc_ln_b, B_);
    zero_k<<<(BB*DD+255)/256, 256>>>(CM, BB*DD);
    colsum_k<<<dim3(2,8,BB), 256>>>(B_, CM);
    colsub_k<<<(BLD/4)/256, 256>>>(B_, CM, ENC, ECH, ECL);

    // ---- decoder ----
    embed_k<<<dim3(2, LL/8, BB), 256>>>(SEAS, x_mark_dec, W_dec_tok, W_dec_tem, A_, S1H, S1L);
    run_attn(2, A_, S1H, S1L, S1H, S1L, dec_self_b,
             B_, V, QT, KT, SP, WW, DL, MH, ML, BVO4);
    decomp_k<<<dim3(2,8,BB), 256>>>(B_, A_, T123, DD, 1, S1H, S1L);
    run_attn(3, A_, S1H, S1L, ECH, ECL, dec_cross_b,
             B_, V, QT, KT, SP, WW, DL, MH, ML, BVO4);
    decomp_k<<<dim3(2,8,BB), 256>>>(B_, A_, T123, DD, 2, S1H, S1L);
    gemm_tc(S1H, S1L, F1H + (size_t)2*DD*DFF, F1L + (size_t)2*DD*DFF,
            nullptr, nullptr, nullptr, S2H, S2L, nullptr, DFF, DD, 1);
    gemm_tc(S2H, S2L, F2H + (size_t)2*DFF*DD, F2L + (size_t)2*DFF*DD,
            nullptr, A_, B_, nullptr, nullptr, nullptr, DD, DFF, 0);
    decomp_k<<<dim3(2,8,BB), 256>>>(B_, A_, T123, DD, 2, S1H, S1L);
    trendconv_k<<<(BL7+255)/256, 256>>>(T123, dec_trend_W, TRD);
    ln_k<<<MROWS, 256>>>(A_, dec_ln_w, dec_ln_b, B_);
    zero_k<<<(BB*DD+255)/256, 256>>>(CM, BB*DD);
    colsum_k<<<dim3(2,8,BB), 256>>>(B_, CM);
    colsub_k<<<(BLD/4)/256, 256>>>(B_, CM, A_, nullptr, nullptr);
    final_k<<<(BB*512*CIN+255)/256, 256>>>(A_, proj_W, proj_b, TRD, out);
}

// round 16
// speedup vs baseline: 1.2948x; 1.2144x over previous
#include <cuda_runtime.h>
#include <cuda_bf16.h>
#include <cuda_fp16.h>
#include <math.h>

// ---------------- constants ----------------
#define BB   32
#define LL   1024
#define DD   512
#define NH   8
#define HE   64
#define DFF  2048
#define CIN  7
#define MK   4
#define MROWS (BB*LL)          // 32768
#define BLD  (BB*LL*DD)        // 16777216
#define BL7  (BB*LL*CIN)       // 229376
#define TOPK 6

typedef __nv_bfloat16 bf16;
typedef __half hf;

// ---------------- device scratch ----------------
__device__ float g_A   [BLD];
__device__ float g_Bf  [BLD];
__device__ float g_v   [BLD];
__device__ float g_enc [BLD];
__device__ float g_t123[BLD];
__device__ float g_qt  [BLD];
__device__ float g_kt  [BLD];
__device__ float2 g_Sp [BB*NH*4*LL];
__device__ float g_cm  [BB*DD];
__device__ float g_w   [BB*8];
__device__ int   g_dly [BB*8];
__device__ float g_sx  [BL7];
__device__ float g_tx  [BL7];
__device__ float g_seas[BL7];
__device__ float g_trd [BL7];
__device__ float g_menc[BB*CIN];
// fused V weights (4 attentions)
__device__ float g_wvo4[4*DD*DD];     // Wv @ Wo
__device__ float g_bvo4[4*DD];        // bv@Wo + bo
// bf16 split buffers (Q/K path)
__device__ bf16 g_mh [8*DD*DD];       // splits: Wq^T[0..3], Wk^T[4..7]
__device__ bf16 g_ml [8*DD*DD];
__device__ bf16 g_s1h[MROWS*DD];
__device__ bf16 g_s1l[MROWS*DD];
__device__ bf16 g_ench[MROWS*DD];
__device__ bf16 g_encl[MROWS*DD];
// fp16 path (V*Wo + FF)
__device__ hf g_vh [4*DD*DD];         // WVO^T fp16 hi
__device__ hf g_vl [4*DD*DD];
__device__ hf g_f1h[3*DD*DFF];
__device__ hf g_f1l[3*DD*DFF];
__device__ hf g_f2h[3*DFF*DD];
__device__ hf g_f2l[3*DFF*DD];
__device__ hf g_x1f[MROWS*DD];        // activations fp16 single
__device__ hf g_ecf[MROWS*DD];
__device__ hf g_x2f[MROWS*DFF];       // FF mid fp16 single

struct P4 { const float* p[4]; };
struct P3 { const float* p[3]; };

// ---------------- helpers ----------------
__device__ __forceinline__ void bsplit(float x, bf16& h, bf16& l){
    h = __float2bfloat16(x);
    l = __float2bfloat16(x - __bfloat162float(h));
}
__device__ __forceinline__ void hsplit(float x, hf& h, hf& l){
    h = __float2half(x);
    l = __float2half(x - __half2float(h));
}
__device__ __forceinline__ unsigned su32(const void* p){
    return (unsigned)__cvta_generic_to_shared(p);
}
__device__ __forceinline__ void cpa16(unsigned dst, const void* src){
    asm volatile("cp.async.cg.shared.global [%0], [%1], 16;" :: "r"(dst), "l"(src));
}
__device__ __forceinline__ void cpa_commit(){
    asm volatile("cp.async.commit_group;" ::: "memory");
}
__device__ __forceinline__ void cpa_wait2(){
    asm volatile("cp.async.wait_group 2;" ::: "memory");
}
__device__ __forceinline__ void ldsm4(unsigned* r, unsigned addr){
    asm volatile("ldmatrix.sync.aligned.m8n8.x4.shared.b16 {%0,%1,%2,%3}, [%4];"
        : "=r"(r[0]), "=r"(r[1]), "=r"(r[2]), "=r"(r[3]) : "r"(addr));
}
__device__ __forceinline__ void mma16(float* d, const unsigned* a, unsigned b0, unsigned b1){
    asm volatile("mma.sync.aligned.m16n8k16.row.col.f32.bf16.bf16.f32 "
        "{%0,%1,%2,%3},{%4,%5,%6,%7},{%8,%9},{%0,%1,%2,%3};"
        : "+f"(d[0]), "+f"(d[1]), "+f"(d[2]), "+f"(d[3])
        : "r"(a[0]), "r"(a[1]), "r"(a[2]), "r"(a[3]), "r"(b0), "r"(b1));
}
__device__ __forceinline__ void mma16h(float* d, const unsigned* a, unsigned b0, unsigned b1){
    asm volatile("mma.sync.aligned.m16n8k16.row.col.f32.f16.f16.f32 "
        "{%0,%1,%2,%3},{%4,%5,%6,%7},{%8,%9},{%0,%1,%2,%3};"
        : "+f"(d[0]), "+f"(d[1]), "+f"(d[2]), "+f"(d[3])
        : "r"(a[0]), "r"(a[1]), "r"(a[2]), "r"(a[3]), "r"(b0), "r"(b1));
}

// ---------------- split-bf16 mma.sync GEMM (Q/K path; R14 winner) ----------------
#define RSTRIDE 80
#define AREA    10240
#define STAGEB  40960
#define NSTAGE  4
#define GEMM_SMEM (NSTAGE*STAGEB)   // 163840
__global__ void __launch_bounds__(512,1) gemm_mma_k(
    const bf16* __restrict__ Ahp, const bf16* __restrict__ Alp,
    const bf16* __restrict__ Bhp, const bf16* __restrict__ Blp,
    const float* __restrict__ bias, float* __restrict__ Ct, int K)
{
    extern __shared__ __align__(16) char dsm[];
    const int tid = threadIdx.x;
    const int lane = tid & 31, warp = tid >> 5;
    const int wm = warp >> 2, wn = warp & 3;
    const int bx = blockIdx.x, by = blockIdx.y;
    const int S = K >> 5;
    const unsigned sbase = su32(dsm);

    const int lrow = tid >> 2, lc16 = tid & 3;
    const bf16* gA_h = Ahp + (size_t)(by*128 + lrow)*K;
    const bf16* gA_l = Alp + (size_t)(by*128 + lrow)*K;
    const bf16* gB_h = Bhp + (size_t)(bx*128 + lrow)*K;
    const bf16* gB_l = Blp + (size_t)(bx*128 + lrow)*K;
    const unsigned sdst = lrow*RSTRIDE + lc16*16;

    float acc[2][4][4];
#pragma unroll
    for (int i=0;i<2;i++)
#pragma unroll
        for (int j=0;j<4;j++)
#pragma unroll
            for (int t=0;t<4;t++) acc[i][j][t]=0.f;

#pragma unroll
    for (int p=0;p<3;p++){
        if (p < S){
            unsigned b = sbase + p*STAGEB + sdst;
            int gk = p*32 + lc16*8;
            cpa16(b,            gA_h + gk);
            cpa16(b + AREA,     gA_l + gk);
            cpa16(b + 2*AREA,   gB_h + gk);
            cpa16(b + 3*AREA,   gB_l + gk);
        }
        cpa_commit();
    }

    const unsigned arow = (wm*32 + (lane & 15))*RSTRIDE + (lane >> 4)*16;
    const unsigned brow = (wn*32 + (lane & 15))*RSTRIDE + (lane >> 4)*16;

    for (int s=0; s<S; s++){
        cpa_wait2();
        __syncthreads();
        if (s+3 < S){
            unsigned b = sbase + ((s+3) & 3)*STAGEB + sdst;
            int gk = (s+3)*32 + lc16*8;
            cpa16(b,            gA_h + gk);
            cpa16(b + AREA,     gA_l + gk);
            cpa16(b + 2*AREA,   gB_h + gk);
            cpa16(b + 3*AREA,   gB_l + gk);
        }
        cpa_commit();
        const unsigned sb = sbase + (s & 3)*STAGEB;
#pragma unroll
        for (int k16=0; k16<2; k16++){
            const unsigned ko = k16*32;
            unsigned ah[8], al[8], bh[8], bl[8];
            ldsm4(ah,   sb + arow + ko);
            ldsm4(ah+4, sb + arow + ko + 16*RSTRIDE);
            ldsm4(al,   sb + AREA + arow + ko);
            ldsm4(al+4, sb + AREA + arow + ko + 16*RSTRIDE);
            ldsm4(bh,   sb + 2*AREA + brow + ko);
            ldsm4(bh+4, sb + 2*AREA + brow + ko + 16*RSTRIDE);
            ldsm4(bl,   sb + 3*AREA + brow + ko);
            ldsm4(bl+4, sb + 3*AREA + brow + ko + 16*RSTRIDE);
#pragma unroll
            for (int mf=0; mf<2; mf++){
#pragma unroll
                for (int nf=0; nf<4; nf++){
                    int g = (nf>>1)*4 + (nf&1);
                    mma16(acc[mf][nf], ah+mf*4, bh[g], bh[g+2]);
                    mma16(acc[mf][nf], ah+mf*4, bl[g], bl[g+2]);
                    mma16(acc[mf][nf], al+mf*4, bh[g], bh[g+2]);
                }
            }
        }
    }
    __syncthreads();

    // transposed output: stage tile in smem then coalesced write along L
    float* st = (float*)dsm;  // [128 cols][129]
#pragma unroll
    for (int mf=0; mf<2; mf++){
#pragma unroll
        for (int nf=0; nf<4; nf++){
            int rl = wm*32 + mf*16 + (lane>>2);
            int cl = wn*32 + nf*8 + ((lane&3)<<1);
            float* d = acc[mf][nf];
#pragma unroll
            for (int h=0; h<2; h++){
                float b0 = __ldg(&bias[bx*128 + cl]);
                float b1 = __ldg(&bias[bx*128 + cl+1]);
                st[cl*129 + rl + 8*h]     = d[2*h]   + b0;
                st[(cl+1)*129 + rl + 8*h] = d[2*h+1] + b1;
            }
        }
    }
    __syncthreads();
    int gr = by*128;
    int b  = gr >> 10;
    int l0 = gr & 1023;
#pragma unroll
    for (int cc=0; cc<8; cc++){
        int col = warp*8 + cc;
        size_t rowoff = ((size_t)b*DD + bx*128 + col)*LL + l0;
#pragma unroll
        for (int i=0;i<4;i++){
            int r = lane + i*32;
            Ct[rowoff + r] = st[col*129 + r];
        }
    }
}

// ---------------- fp16 2-term GEMM: C = A_fp16 * (Bh + Bl)^T ----------------
// A: MxK fp16 single; B: NxK fp16 split. Outputs: float C (opt bias/gelu/res) or fp16 Cf.
#define STAGE2B 30720
#define GEMM2_SMEM (NSTAGE*STAGE2B)  // 122880
__global__ void __launch_bounds__(512,1) gemm2h_k(
    const hf* __restrict__ Ap,
    const hf* __restrict__ Bhp, const hf* __restrict__ Blp,
    const float* __restrict__ bias, const float* __restrict__ res,
    float* __restrict__ C, hf* __restrict__ Cf,
    int N, int K, int dogelu)
{
    extern __shared__ __align__(16) char dsm[];
    const int tid = threadIdx.x;
    const int lane = tid & 31, warp = tid >> 5;
    const int wm = warp >> 2, wn = warp & 3;
    const int bx = blockIdx.x, by = blockIdx.y;
    const int S = K >> 5;
    const unsigned sbase = su32(dsm);

    const int lrow = tid >> 2, lc16 = tid & 3;
    const hf* gA   = Ap  + (size_t)(by*128 + lrow)*K;
    const hf* gB_h = Bhp + (size_t)(bx*128 + lrow)*K;
    const hf* gB_l = Blp + (size_t)(bx*128 + lrow)*K;
    const unsigned sdst = lrow*RSTRIDE + lc16*16;

    float acc[2][4][4];
#pragma unroll
    for (int i=0;i<2;i++)
#pragma unroll
        for (int j=0;j<4;j++)
#pragma unroll
            for (int t=0;t<4;t++) acc[i][j][t]=0.f;

#pragma unroll
    for (int p=0;p<3;p++){
        if (p < S){
            unsigned b = sbase + p*STAGE2B + sdst;
            int gk = p*32 + lc16*8;
            cpa16(b,            gA   + gk);
            cpa16(b + AREA,     gB_h + gk);
            cpa16(b + 2*AREA,   gB_l + gk);
        }
        cpa_commit();
    }

    const unsigned arow = (wm*32 + (lane & 15))*RSTRIDE + (lane >> 4)*16;
    const unsigned brow = (wn*32 + (lane & 15))*RSTRIDE + (lane >> 4)*16;

    for (int s=0; s<S; s++){
        cpa_wait2();
        __syncthreads();
        if (s+3 < S){
            unsigned b = sbase + ((s+3) & 3)*STAGE2B + sdst;
            int gk = (s+3)*32 + lc16*8;
            cpa16(b,            gA   + gk);
            cpa16(b + AREA,     gB_h + gk);
            cpa16(b + 2*AREA,   gB_l + gk);
        }
        cpa_commit();
        const unsigned sb = sbase + (s & 3)*STAGE2B;
#pragma unroll
        for (int k16=0; k16<2; k16++){
            const unsigned ko = k16*32;
            unsigned ah[8], bh[8], bl[8];
            ldsm4(ah,   sb + arow + ko);
            ldsm4(ah+4, sb + arow + ko + 16*RSTRIDE);
            ldsm4(bh,   sb + AREA + brow + ko);
            ldsm4(bh+4, sb + AREA + brow + ko + 16*RSTRIDE);
            ldsm4(bl,   sb + 2*AREA + brow + ko);
            ldsm4(bl+4, sb + 2*AREA + brow + ko + 16*RSTRIDE);
#pragma unroll
            for (int mf=0; mf<2; mf++){
#pragma unroll
                for (int nf=0; nf<4; nf++){
                    int g = (nf>>1)*4 + (nf&1);
                    mma16h(acc[mf][nf], ah+mf*4, bh[g], bh[g+2]);
                    mma16h(acc[mf][nf], ah+mf*4, bl[g], bl[g+2]);
                }
            }
        }
    }

#pragma unroll
    for (int mf=0; mf<2; mf++){
#pragma unroll
        for (int nf=0; nf<4; nf++){
            int r0  = by*128 + wm*32 + mf*16 + (lane>>2);
            int col = bx*128 + wn*32 + nf*8 + ((lane&3)<<1);
            float* d = acc[mf][nf];
#pragma unroll
            for (int h=0; h<2; h++){
                int r = r0 + h*8;
                size_t rowoff = (size_t)r * N;
                float2 o = make_float2(d[2*h], d[2*h+1]);
                if (bias){ o.x += __ldg(&bias[col]); o.y += __ldg(&bias[col+1]); }
                if (dogelu){
                    o.x = 0.5f*o.x*(1.0f+erff(o.x*0.7071067811865476f));
                    o.y = 0.5f*o.y*(1.0f+erff(o.y*0.7071067811865476f));
                }
                if (res){
                    float2 rr = *(const float2*)&res[rowoff + col];
                    o.x += rr.x; o.y += rr.y;
                }
                if (Cf){
                    __half2 hv; hv.x = __float2half(o.x); hv.y = __float2half(o.y);
                    *(__half2*)&Cf[rowoff + col] = hv;
                } else {
                    *(float2*)&C[rowoff + col] = o;
                }
            }
        }
    }
}

// ---------------- batched 512x512 matmuls: WVO[z] = Wv @ Wo ----------------
__global__ void mmvo_b_k(P4 wb, float* __restrict__ wvo){
    __shared__ float As[32][33], Bs[32][33];
    int z = blockIdx.z;
    const float* A = wb.p[z] + (size_t)2*DD*DD;
    const float* B = wb.p[z] + (size_t)3*DD*DD;
    float* C = wvo + (size_t)z*DD*DD;
    int i0 = blockIdx.y*32, j0 = blockIdx.x*32;
    int tx = threadIdx.x, ty = threadIdx.y;
    float acc[4] = {0.f,0.f,0.f,0.f};
    for (int k0=0;k0<512;k0+=32){
        for (int r=ty;r<32;r+=8){
            As[r][tx] = A[(size_t)(i0+r)*512 + k0+tx];
            Bs[r][tx] = B[(size_t)(k0+r)*512 + j0+tx];
        }
        __syncthreads();
#pragma unroll
        for (int k=0;k<32;k++){
            float bv = Bs[k][tx];
#pragma unroll
            for (int u=0;u<4;u++) acc[u] += As[ty+8*u][k]*bv;
        }
        __syncthreads();
    }
#pragma unroll
    for (int u=0;u<4;u++) C[(size_t)(i0+ty+8*u)*512 + j0+tx] = acc[u];
}

// ---------------- batched fused bias: bvo[z] = bv@Wo + bo ----------------
__global__ void biasvo_b_k(P4 bb, P4 wb, float* __restrict__ bvo){
    int z = blockIdx.y;
    int j = blockIdx.x*256 + threadIdx.x;
    if (j >= 512) return;
    const float* bv = bb.p[z] + 2*DD;
    const float* bo = bb.p[z] + 3*DD;
    const float* Wo = wb.p[z] + (size_t)3*DD*DD;
    float s = bo[j];
    for (int m=0;m<512;m++) s += bv[m]*Wo[(size_t)m*512 + j];
    bvo[z*DD + j] = s;
}

// ---------------- batched split+transpose of 8 512x512 mats (Wq, Wk; bf16) ----------------
__global__ void split512b_k(P4 wb, bf16* __restrict__ oh, bf16* __restrict__ ol){
    __shared__ float t[32][33];
    int z = blockIdx.z;
    const float* W = (z < 4) ? wb.p[z] : wb.p[z-4] + (size_t)DD*DD;
    bf16* ohp = oh + (size_t)z*DD*DD;
    bf16* olp = ol + (size_t)z*DD*DD;
    int n0 = blockIdx.x*32, k0 = blockIdx.y*32;
    int x = threadIdx.x, y = threadIdx.y;
    for (int i=y;i<32;i+=8)
        t[i][x] = W[(size_t)(k0+i)*DD + n0 + x];
    __syncthreads();
    for (int i=y;i<32;i+=8){
        float v = t[x][i];
        bf16 h,l; bsplit(v,h,l);
        ohp[(size_t)(n0+i)*DD + k0 + x] = h;
        olp[(size_t)(n0+i)*DD + k0 + x] = l;
    }
}

// ---------------- WVO fp16 split+transpose (4 mats) ----------------
__global__ void splitvoh_k(const float* __restrict__ wvo, hf* __restrict__ oh,
                           hf* __restrict__ ol){
    __shared__ float t[32][33];
    int z = blockIdx.z;
    const float* W = wvo + (size_t)z*DD*DD;
    hf* ohp = oh + (size_t)z*DD*DD;
    hf* olp = ol + (size_t)z*DD*DD;
    int n0 = blockIdx.x*32, k0 = blockIdx.y*32;
    int x = threadIdx.x, y = threadIdx.y;
    for (int i=y;i<32;i+=8)
        t[i][x] = W[(size_t)(k0+i)*DD + n0 + x];
    __syncthreads();
    for (int i=y;i<32;i+=8){
        float v = t[x][i];
        hf h,l; hsplit(v,h,l);
        ohp[(size_t)(n0+i)*DD + k0 + x] = h;
        olp[(size_t)(n0+i)*DD + k0 + x] = l;
    }
}

// ---------------- FF weight fp16 split+transpose ----------------
__global__ void splitffh_k(P3 Wl, hf* __restrict__ oh, hf* __restrict__ ol,
                           int Kd, int Nd){
    __shared__ float t[32][33];
    int z = blockIdx.z;
    const float* W = Wl.p[z];
    hf* ohp = oh + (size_t)z*Kd*Nd;
    hf* olp = ol + (size_t)z*Kd*Nd;
    int n0 = blockIdx.x*32, k0 = blockIdx.y*32;
    int x = threadIdx.x, y = threadIdx.y;
    for (int i=y;i<32;i+=8)
        t[i][x] = W[(size_t)(k0+i)*Nd + n0 + x];
    __syncthreads();
    for (int i=y;i<32;i+=8){
        float v = t[x][i];
        hf h,l; hsplit(v,h,l);
        ohp[(size_t)(n0+i)*Kd + k0 + x] = h;
        olp[(size_t)(n0+i)*Kd + k0 + x] = l;
    }
}

// ---------------- FFT helpers ----------------
__device__ __forceinline__ float2 cmul(float2 a, float2 b){
    return make_float2(a.x*b.x - a.y*b.y, a.x*b.y + a.y*b.x);
}
__device__ __forceinline__ int dig4rev(int t){
    int br = __brev(t) >> 22;
    return ((br >> 1) & 0x155) | ((br << 1) & 0x2AA);
}
__device__ void fft1024_r4(float2* z, const float2* tw, int tid, int inv){
    const float s4 = inv ? 1.0f : -1.0f;
#pragma unroll
    for (int s=0; s<5; s++){
        __syncthreads();
        const int quarter = 1 << (2*s);
        const int pos = tid & (quarter-1);
        const int g   = tid >> (2*s);
        const int base = (g << (2*s+2)) + pos;
        const int tstep = pos << (8 - 2*s);
        float2 x0 = z[base];
        float2 x1 = cmul(tw[tstep],   z[base + quarter]);
        float2 x2 = cmul(tw[2*tstep], z[base + 2*quarter]);
        float2 x3 = cmul(tw[3*tstep], z[base + 3*quarter]);
        float2 t0 = make_float2(x0.x+x2.x, x0.y+x2.y);
        float2 t1 = make_float2(x0.x-x2.x, x0.y-x2.y);
        float2 t2 = make_float2(x1.x+x3.x, x1.y+x3.y);
        float2 t3 = make_float2(x1.x-x3.x, x1.y-x3.y);
        float2 rot = make_float2(-s4*t3.y, s4*t3.x);
        z[base]             = make_float2(t0.x+t2.x, t0.y+t2.y);
        z[base+quarter]     = make_float2(t1.x+rot.x, t1.y+rot.y);
        z[base+2*quarter]   = make_float2(t0.x-t2.x, t0.y-t2.y);
        z[base+3*quarter]   = make_float2(t1.x-rot.x, t1.y-rot.y);
    }
    __syncthreads();
}

#define EPB 16
__global__ void corr_fwd_k(const float* __restrict__ qt, const float* __restrict__ kt,
                           float2* __restrict__ Sp){
    __shared__ float2 z[1024];
    __shared__ float2 acc[1024];
    __shared__ float2 tw[1024];
    int bh = blockIdx.x;
    int chunk = blockIdx.y;
    int tid = threadIdx.x;
    for (int j=tid;j<1024;j+=256){
        float s,c; sincosf((float)j * (6.283185307179586f/1024.0f), &s, &c);
        tw[j] = make_float2(c, -s);
    }
    for (int f=tid;f<1024;f+=256) acc[f] = make_float2(0.f,0.f);
    for (int ei=0; ei<EPB; ei++){
        int e = chunk*EPB + ei;
        const float* qp = qt + ((size_t)bh*HE + e)*LL;
        const float* kp = kt + ((size_t)bh*HE + e)*LL;
        __syncthreads();
        for (int t=tid;t<1024;t+=256){
            z[dig4rev(t)] = make_float2(qp[t], kp[t]);
        }
        fft1024_r4(z, tw, tid, 0);
        for (int f=tid;f<1024;f+=256){
            float2 Zf = z[f];
            float2 Zm = z[(1024 - f) & 1023];
            float2 Zc = make_float2(Zm.x, -Zm.y);
            float2 Q  = make_float2(0.5f*(Zf.x+Zc.x), 0.5f*(Zf.y+Zc.y));
            float dx = Zf.x - Zc.x, dy = Zf.y - Zc.y;
            float2 Kk = make_float2(0.5f*dy, -0.5f*dx);
            acc[f].x += Q.x*Kk.x + Q.y*Kk.y;
            acc[f].y += Q.y*Kk.x - Q.x*Kk.y;
        }
    }
    __syncthreads();
    float2* dst = Sp + ((size_t)bh*4 + chunk)*LL;
    for (int f=tid;f<1024;f+=256) dst[f] = acc[f];
}

__global__ void corr_topk_k(const float2* __restrict__ Sp, float* __restrict__ wout,
                            int* __restrict__ dout){
    __shared__ float2 z[1024];
    __shared__ float2 tw[1024];
    __shared__ float corr[1024];
    __shared__ float rv[256];
    __shared__ int   ri[256];
    __shared__ float wv[TOPK];
    __shared__ int   dv[TOPK];
    int b = blockIdx.x, tid = threadIdx.x;
    for (int j=tid;j<1024;j+=256){
        float s,c; sincosf((float)j * (6.283185307179586f/1024.0f), &s, &c);
        tw[j] = make_float2(c, s);   // inverse
    }
    for (int f=tid;f<1024;f+=256){
        float sx=0.f, sy=0.f;
        const float2* sp = Sp + (size_t)b*32*LL + f;
#pragma unroll
        for (int sl=0;sl<32;sl++){
            float2 v = sp[(size_t)sl*LL];
            sx += v.x; sy += v.y;
        }
        z[dig4rev(f)] = make_float2(sx, sy);
    }
    fft1024_r4(z, tw, tid, 1);
    const float scale = 1.0f / (1024.0f * 512.0f);
    for (int f=tid;f<1024;f+=256) corr[f] = z[f].x * scale;
    __syncthreads();
    for (int it=0; it<TOPK; it++){
        float best = -1e30f; int bi = 1<<30;
        for (int f=tid;f<1024;f+=256){
            float v = corr[f];
            if (v > best || (v == best && f < bi)){ best = v; bi = f; }
        }
        rv[tid]=best; ri[tid]=bi; __syncthreads();
        for (int off=128; off; off>>=1){
            if (tid < off){
                if (rv[tid+off] > rv[tid] || (rv[tid+off]==rv[tid] && ri[tid+off]<ri[tid])){
                    rv[tid]=rv[tid+off]; ri[tid]=ri[tid+off];
                }
            }
            __syncthreads();
        }
        if (tid==0){ wv[it]=rv[0]; dv[it]=ri[0]; corr[ri[0]] = -1e30f; }
        __syncthreads();
    }
    if (tid==0){
        float mx = wv[0];
        float ex[TOPK]; float s=0.f;
        for (int i=0;i<TOPK;i++){ ex[i]=expf(wv[i]-mx); s+=ex[i]; }
        for (int i=0;i<TOPK;i++){ wout[b*8+i]=ex[i]/s; dout[b*8+i]=dv[i]; }
    }
}

// ---------------- roll & weight + residual (float4) ----------------
__global__ void roll_res_k(const float* __restrict__ P, const float* __restrict__ w,
                           const int* __restrict__ d, const float* __restrict__ res,
                           float* __restrict__ out){
    int idx = blockIdx.x*256 + threadIdx.x;
    if (idx >= BLD/4) return;
    int c4 = idx & 127;
    int t = (idx >> 7) & (LL-1);
    int b = idx >> 17;
    float4 s = __ldg(&((const float4*)res)[idx]);
#pragma unroll
    for (int i=0;i<TOPK;i++){
        int   dl = __ldg(&d[b*8+i]);
        float wi = __ldg(&w[b*8+i]);
        int tt = (t + dl) & (LL-1);
        float4 v = __ldg(&((const float4*)P)[((size_t)(b*LL + tt) << 7) + c4]);
        s.x += wi*v.x; s.y += wi*v.y; s.z += wi*v.z; s.w += wi*v.w;
    }
    ((float4*)out)[idx] = s;
}

// ---------------- series decomposition (moving mean k=25) ----------------
__global__ void decomp_k(const float* __restrict__ x, float* __restrict__ seas,
                         float* __restrict__ trend, int C, int mode,
                         bf16* __restrict__ oh, bf16* __restrict__ ol,
                         hf* __restrict__ of){
    int b = blockIdx.z;
    int c = blockIdx.x*blockDim.x + threadIdx.x;
    if (c >= C) return;
    int l0 = blockIdx.y * 128;
    const float* xb = x + (size_t)b*LL*C + c;
    float sum = 0.f;
    for (int j=l0-12;j<=l0+12;j++){
        int jj = min(max(j,0), LL-1);
        sum += xb[(size_t)jj*C];
    }
    for (int l=l0; l<l0+128; l++){
        float m = sum * (1.0f/25.0f);
        size_t o = (size_t)b*LL*C + (size_t)l*C + c;
        float sv = x[o] - m;
        seas[o] = sv;
        if (oh){
            bf16 h,lo; bsplit(sv,h,lo); oh[o]=h; ol[o]=lo;
            of[o] = __float2half(sv);
        }
        if (mode==1) trend[o] = m;
        else if (mode==2) trend[o] += m;
        int ja = min(l+13, LL-1), jr = max(l-12, 0);
        sum += xb[(size_t)ja*C] - xb[(size_t)jr*C];
    }
}

// ---------------- layernorm over feature dim ----------------
__global__ void ln_k(const float* __restrict__ x, const float* __restrict__ w,
                     const float* __restrict__ bv, float* __restrict__ y){
    __shared__ float red[256];
    int row = blockIdx.x, tid = threadIdx.x;
    const float* xr = x + (size_t)row*DD;
    float v0 = xr[tid], v1 = xr[tid+256];
    red[tid] = v0+v1; __syncthreads();
    for (int o=128;o;o>>=1){ if (tid<o) red[tid]+=red[tid+o]; __syncthreads(); }
    float mu = red[0]*(1.0f/512.0f);
    __syncthreads();
    float d0=v0-mu, d1=v1-mu;
    red[tid] = d0*d0+d1*d1; __syncthreads();
    for (int o=128;o;o>>=1){ if (tid<o) red[tid]+=red[tid+o]; __syncthreads(); }
    float rstd = rsqrtf(red[0]*(1.0f/512.0f) + 1e-5f);
    y[(size_t)row*DD + tid]     = d0*rstd*w[tid]     + bv[tid];
    y[(size_t)row*DD + tid+256] = d1*rstd*w[tid+256] + bv[tid+256];
}

// ---------------- column (time) mean ----------------
__global__ void zero_k(float* p, int n){
    int i = blockIdx.x*blockDim.x + threadIdx.x;
    if (i < n) p[i] = 0.0f;
}
__global__ void colsum_k(const float* __restrict__ x, float* __restrict__ cm){
    int b = blockIdx.z;
    int c = blockIdx.x*256 + threadIdx.x;
    int l0 = blockIdx.y*128;
    float s=0.f;
    for (int l=l0;l<l0+128;l++) s += x[((size_t)b*LL + l)*DD + c];
    atomicAdd(&cm[b*DD + c], s);
}
__global__ void colsub_k(const float* __restrict__ x, const float* __restrict__ cm,
                         float* __restrict__ y, bf16* __restrict__ oh, bf16* __restrict__ ol,
                         hf* __restrict__ of){
    int idx = blockIdx.x*256 + threadIdx.x;
    if (idx >= BLD/4) return;
    int c4 = idx & 127;
    int b = idx >> 17;
    float4 xv = __ldg(&((const float4*)x)[idx]);
    float4 cv = __ldg(&((const float4*)cm)[b*128 + c4]);
    float4 v;
    v.x = xv.x - cv.x*(1.0f/1024.0f);
    v.y = xv.y - cv.y*(1.0f/1024.0f);
    v.z = xv.z - cv.z*(1.0f/1024.0f);
    v.w = xv.w - cv.w*(1.0f/1024.0f);
    ((float4*)y)[idx] = v;
    if (oh){
        bf16 h0,l0,h1,l1,h2,l2,h3,l3;
        bsplit(v.x,h0,l0); bsplit(v.y,h1,l1); bsplit(v.z,h2,l2); bsplit(v.w,h3,l3);
        __nv_bfloat162* oh2 = (__nv_bfloat162*)oh;
        __nv_bfloat162* ol2 = (__nv_bfloat162*)ol;
        __nv_bfloat162 a,bb2;
        a.x=h0; a.y=h1; bb2.x=h2; bb2.y=h3;
        oh2[2*idx]=a; oh2[2*idx+1]=bb2;
        a.x=l0; a.y=l1; bb2.x=l2; bb2.y=l3;
        ol2[2*idx]=a; ol2[2*idx+1]=bb2;
        __half2* of2 = (__half2*)of;
        __half2 f0; f0.x=__float2half(v.x); f0.y=__float2half(v.y);
        __half2 f1; f1.x=__float2half(v.z); f1.y=__float2half(v.w);
        of2[2*idx]=f0; of2[2*idx+1]=f1;
    }
}

// ---------------- embedding (weight-register reuse, 8 l per thread) ----------------
__global__ void embed_k(const float* __restrict__ x, const float* __restrict__ mark,
                        const float* __restrict__ Wtok, const float* __restrict__ Wtem,
                        float* __restrict__ out, bf16* __restrict__ oh, bf16* __restrict__ ol,
                        hf* __restrict__ of){
    int d = blockIdx.x*256 + threadIdx.x;
    int b = blockIdx.z;
    int l0 = blockIdx.y*8;
    float w[21], wt[4];
#pragma unroll
    for (int i=0;i<21;i++) w[i] = __ldg(&Wtok[(size_t)i*DD + d]);
#pragma unroll
    for (int m=0;m<MK;m++) wt[m] = __ldg(&Wtem[(size_t)m*DD + d]);
#pragma unroll
    for (int i=0;i<8;i++){
        int l = l0 + i;
        int lm = (l + LL - 1) & (LL-1), lp = (l + 1) & (LL-1);
        const float* x0 = x + ((size_t)b*LL + lm)*CIN;
        const float* x1 = x + ((size_t)b*LL + l )*CIN;
        const float* x2 = x + ((size_t)b*LL + lp)*CIN;
        float s = 0.f;
#pragma unroll
        for (int c=0;c<CIN;c++){
            s += x0[c]*w[c];
            s += x1[c]*w[7+c];
            s += x2[c]*w[14+c];
        }
        const float* mk = mark + ((size_t)b*LL + l)*MK;
#pragma unroll
        for (int m=0;m<MK;m++) s += mk[m]*wt[m];
        size_t o = ((size_t)b*LL + l)*DD + d;
        out[o] = s;
        bf16 h,lo; bsplit(s,h,lo); oh[o]=h; ol[o]=lo;
        of[o] = __float2half(s);
    }
}

// ---------------- mean of x_enc over time ----------------
__global__ void meanenc_k(const float* __restrict__ x, float* __restrict__ m){
    __shared__ float red[256];
    int b = blockIdx.x / CIN, c = blockIdx.x % CIN;
    int tid = threadIdx.x;
    float s=0.f;
    for (int l=tid;l<LL;l+=256) s += x[((size_t)b*LL + l)*CIN + c];
    red[tid]=s; __syncthreads();
    for (int o=128;o;o>>=1){ if (tid<o) red[tid]+=red[tid+o]; __syncthreads(); }
    if (tid==0) m[blockIdx.x] = red[0]*(1.0f/1024.0f);
}

__global__ void decinit_k(const float* __restrict__ sx, const float* __restrict__ tx,
                          const float* __restrict__ menc, float* __restrict__ seas,
                          float* __restrict__ trend){
    int idx = blockIdx.x*256 + threadIdx.x;
    if (idx >= BL7) return;
    int c = idx % CIN;
    int l = (idx / CIN) % LL;
    int b = idx / (CIN*LL);
    if (l < 512){
        size_t src = ((size_t)b*LL + 512 + l)*CIN + c;
        seas[idx]  = sx[src];
        trend[idx] = tx[src];
    } else {
        seas[idx]  = 0.f;
        trend[idx] = menc[b*CIN + c];
    }
}

__global__ void trendconv_k(const float* __restrict__ t123, const float* __restrict__ Wt,
                            float* __restrict__ trend){
    int idx = blockIdx.x*256 + threadIdx.x;
    if (idx >= BL7) return;
    int c = idx % CIN;
    int l = (idx / CIN) % LL;
    int b = idx / (CIN*LL);
    int lm = (l + LL - 1) & (LL-1), lp = (l + 1) & (LL-1);
    const float* r0 = t123 + ((size_t)b*LL + lm)*DD;
    const float* r1 = t123 + ((size_t)b*LL + l )*DD;
    const float* r2 = t123 + ((size_t)b*LL + lp)*DD;
    float s = 0.f;
    for (int d=0; d<DD; d++){
        s += r0[d]*__ldg(&Wt[(0*DD+d)*CIN + c]);
        s += r1[d]*__ldg(&Wt[(1*DD+d)*CIN + c]);
        s += r2[d]*__ldg(&Wt[(2*DD+d)*CIN + c]);
    }
    trend[idx] += s;
}

__global__ void final_k(const float* __restrict__ dec, const float* __restrict__ projW,
                        const float* __restrict__ projb, const float* __restrict__ trend,
                        float* __restrict__ out){
    int idx = blockIdx.x*256 + threadIdx.x;
    if (idx >= BB*512*CIN) return;
    int c = idx % CIN;
    int lp = (idx / CIN) % 512;
    int b = idx / (512*CIN);
    int l = 512 + lp;
    const float* r = dec + ((size_t)b*LL + l)*DD;
    float s = projb[c];
    for (int d=0; d<DD; d++) s += r[d]*__ldg(&projW[d*CIN + c]);
    out[idx] = trend[((size_t)b*LL + l)*CIN + c] + s;
}

// ---------------- host orchestration ----------------
static void gemm_qk(const bf16* ah, const bf16* al, const bf16* bh, const bf16* bl,
                    const float* bias, float* Ct){
    dim3 g(DD/128, MROWS/128);
    gemm_mma_k<<<g, 512, GEMM_SMEM>>>(ah, al, bh, bl, bias, Ct, DD);
}
static void gemm2h(const hf* a, const hf* bh, const hf* bl,
                   const float* bias, const float* res,
                   float* C, hf* Cf, int N, int K, int gelu){
    dim3 g(N/128, MROWS/128);
    gemm2h_k<<<g, 512, GEMM2_SMEM>>>(a, bh, bl, bias, res, C, Cf, N, K, gelu);
}

static void run_attn(int ai, const float* res,
                     const bf16* xqh, const bf16* xql,
                     const bf16* xkvh, const bf16* xkvl, const hf* xkvf,
                     const float* bias, float* outb, float* Pv,
                     float* qt, float* kt, float2* Sp, float* wbuf, int* dbuf,
                     bf16* MH, bf16* ML, hf* VH, hf* VL, float* BVO4){
    gemm_qk(xqh, xql,  MH + (size_t)ai*DD*DD,     ML + (size_t)ai*DD*DD,
            bias, qt);
    gemm_qk(xkvh, xkvl, MH + (size_t)(4+ai)*DD*DD, ML + (size_t)(4+ai)*DD*DD,
            bias + DD, kt);
    gemm2h(xkvf, VH + (size_t)ai*DD*DD, VL + (size_t)ai*DD*DD,
           BVO4 + ai*DD, nullptr, Pv, nullptr, DD, DD, 0);
    corr_fwd_k<<<dim3(BB*NH, 4), 256>>>(qt, kt, Sp);
    corr_topk_k<<<BB, 256>>>(Sp, wbuf, dbuf);
    roll_res_k<<<(BLD/4)/256, 256>>>(Pv, wbuf, dbuf, res, outb);
}

extern "C" void kernel_launch(void* const* d_in, const int* in_sizes, int n_in,
                              void* d_out, int out_size){
    const float* x_enc      = (const float*)d_in[0];
    const float* x_mark_enc = (const float*)d_in[1];
    const float* x_mark_dec = (const float*)d_in[3];
    const float* W_enc_tok  = (const float*)d_in[4];
    const float* W_enc_tem  = (const float*)d_in[5];
    const float* W_dec_tok  = (const float*)d_in[6];
    const float* W_dec_tem  = (const float*)d_in[7];
    const float* enc_attn_W = (const float*)d_in[8];
    const float* enc_attn_b = (const float*)d_in[9];
    const float* enc_ff1    = (const float*)d_in[10];
    const float* enc_ff2    = (const float*)d_in[11];
    const float* enc_ln_w   = (const float*)d_in[12];
    const float* enc_ln_b   = (const float*)d_in[13];
    const float* dec_self_W = (const float*)d_in[14];
    const float* dec_self_b = (const float*)d_in[15];
    const float* dec_cross_W= (const float*)d_in[16];
    const float* dec_cross_b= (const float*)d_in[17];
    const float* dec_ff1    = (const float*)d_in[18];
    const float* dec_ff2    = (const float*)d_in[19];
    const float* dec_trend_W= (const float*)d_in[20];
    const float* dec_ln_w   = (const float*)d_in[21];
    const float* dec_ln_b   = (const float*)d_in[22];
    const float* proj_W     = (const float*)d_in[23];
    const float* proj_b     = (const float*)d_in[24];
    float* out = (float*)d_out;

    cudaFuncSetAttribute(gemm_mma_k, cudaFuncAttributeMaxDynamicSharedMemorySize, GEMM_SMEM);
    cudaFuncSetAttribute(gemm2h_k,  cudaFuncAttributeMaxDynamicSharedMemorySize, GEMM2_SMEM);

    void *pA,*pB,*pv,*penc,*pt123,*pqt,*pkt,*pSp,*pcm,*pw,*pd;
    void *psx,*ptx,*pseas,*ptrd,*pmenc,*pwvo,*pbvo;
    void *ps1h,*ps1l,*pech,*pecl;
    void *pmh,*pml,*pvh,*pvl,*pf1h,*pf1l,*pf2h,*pf2l,*px1f,*pecf,*px2f;
    cudaGetSymbolAddress(&pA, g_A);       cudaGetSymbolAddress(&pB, g_Bf);
    cudaGetSymbolAddress(&pv, g_v);       cudaGetSymbolAddress(&penc, g_enc);
    cudaGetSymbolAddress(&pt123, g_t123);
    cudaGetSymbolAddress(&pqt, g_qt);     cudaGetSymbolAddress(&pkt, g_kt);
    cudaGetSymbolAddress(&pSp, g_Sp);     cudaGetSymbolAddress(&pcm, g_cm);
    cudaGetSymbolAddress(&pw, g_w);       cudaGetSymbolAddress(&pd, g_dly);
    cudaGetSymbolAddress(&psx, g_sx);     cudaGetSymbolAddress(&ptx, g_tx);
    cudaGetSymbolAddress(&pseas, g_seas); cudaGetSymbolAddress(&ptrd, g_trd);
    cudaGetSymbolAddress(&pmenc, g_menc);
    cudaGetSymbolAddress(&pwvo, g_wvo4);  cudaGetSymbolAddress(&pbvo, g_bvo4);
    cudaGetSymbolAddress(&ps1h, g_s1h);   cudaGetSymbolAddress(&ps1l, g_s1l);
    cudaGetSymbolAddress(&pech, g_ench);  cudaGetSymbolAddress(&pecl, g_encl);
    cudaGetSymbolAddress(&pmh, g_mh);     cudaGetSymbolAddress(&pml, g_ml);
    cudaGetSymbolAddress(&pvh, g_vh);     cudaGetSymbolAddress(&pvl, g_vl);
    cudaGetSymbolAddress(&pf1h, g_f1h);   cudaGetSymbolAddress(&pf1l, g_f1l);
    cudaGetSymbolAddress(&pf2h, g_f2h);   cudaGetSymbolAddress(&pf2l, g_f2l);
    cudaGetSymbolAddress(&px1f, g_x1f);   cudaGetSymbolAddress(&pecf, g_ecf);
    cudaGetSymbolAddress(&px2f, g_x2f);

    float *A_=(float*)pA, *B_=(float*)pB, *V=(float*)pv;
    float *ENC=(float*)penc, *T123=(float*)pt123, *QT=(float*)pqt, *KT=(float*)pkt;
    float2 *SP=(float2*)pSp;
    float *CM=(float*)pcm, *WW=(float*)pw; int *DL=(int*)pd;
    float *SX=(float*)psx, *TX=(float*)ptx, *SEAS=(float*)pseas, *TRD=(float*)ptrd, *MENC=(float*)pmenc;
    float *WVO4=(float*)pwvo, *BVO4=(float*)pbvo;
    bf16 *S1H=(bf16*)ps1h, *S1L=(bf16*)ps1l, *ECH=(bf16*)pech, *ECL=(bf16*)pecl;
    bf16 *MH=(bf16*)pmh, *ML=(bf16*)pml;
    hf *VH=(hf*)pvh, *VL=(hf*)pvl;
    hf *F1H=(hf*)pf1h, *F1L=(hf*)pf1l, *F2H=(hf*)pf2h, *F2L=(hf*)pf2l;
    hf *X1F=(hf*)px1f, *ECF=(hf*)pecf, *X2F=(hf*)px2f;

    // ---- batched weight prep ----
    P4 wb; wb.p[0]=enc_attn_W; wb.p[1]=enc_attn_W + (size_t)4*DD*DD;
           wb.p[2]=dec_self_W; wb.p[3]=dec_cross_W;
    P4 bb; bb.p[0]=enc_attn_b; bb.p[1]=enc_attn_b + 4*DD;
           bb.p[2]=dec_self_b; bb.p[3]=dec_cross_b;
    mmvo_b_k<<<dim3(16,16,4), dim3(32,8)>>>(wb, WVO4);
    biasvo_b_k<<<dim3(2,4), 256>>>(bb, wb, BVO4);
    split512b_k<<<dim3(16,16,8), dim3(32,8)>>>(wb, MH, ML);
    splitvoh_k<<<dim3(16,16,4), dim3(32,8)>>>(WVO4, VH, VL);
    P3 f1; f1.p[0]=enc_ff1; f1.p[1]=enc_ff1 + (size_t)DD*DFF; f1.p[2]=dec_ff1;
    P3 f2; f2.p[0]=enc_ff2; f2.p[1]=enc_ff2 + (size_t)DFF*DD; f2.p[2]=dec_ff2;
    splitffh_k<<<dim3(64,16,3), dim3(32,8)>>>(f1, F1H, F1L, DD, DFF);
    splitffh_k<<<dim3(16,64,3), dim3(32,8)>>>(f2, F2H, F2L, DFF, DD);

    // ---- decoder init tensors (from x_enc) ----
    decomp_k<<<dim3(1,8,BB), 32>>>(x_enc, SX, TX, CIN, 1, nullptr, nullptr, nullptr);
    meanenc_k<<<BB*CIN, 256>>>(x_enc, MENC);
    decinit_k<<<(BL7+255)/256, 256>>>(SX, TX, MENC, SEAS, TRD);

    // ---- encoder ----
    embed_k<<<dim3(2, LL/8, BB), 256>>>(x_enc, x_mark_enc, W_enc_tok, W_enc_tem,
                                        A_, S1H, S1L, X1F);
    for (int l=0; l<2; l++){
        run_attn(l, A_, S1H, S1L, S1H, S1L, X1F,
                 enc_attn_b + (size_t)l*4*DD,
                 B_, V, QT, KT, SP, WW, DL, MH, ML, VH, VL, BVO4);
        decomp_k<<<dim3(2,8,BB), 256>>>(B_, A_, nullptr, DD, 0, S1H, S1L, X1F);
        gemm2h(X1F, F1H + (size_t)l*DD*DFF, F1L + (size_t)l*DD*DFF,
               nullptr, nullptr, nullptr, X2F, DFF, DD, 1);
        gemm2h(X2F, F2H + (size_t)l*DFF*DD, F2L + (size_t)l*DFF*DD,
               nullptr, A_, B_, nullptr, DD, DFF, 0);
        decomp_k<<<dim3(2,8,BB), 256>>>(B_, A_, nullptr, DD, 0, S1H, S1L, X1F);
    }
    ln_k<<<MROWS, 256>>>(A_, enc_ln_w, enc_ln_b, B_);
    zero_k<<<(BB*DD+255)/256, 256>>>(CM, BB*DD);
    colsum_k<<<dim3(2,8,BB), 256>>>(B_, CM);
    colsub_k<<<(BLD/4)/256, 256>>>(B_, CM, ENC, ECH, ECL, ECF);

    // ---- decoder ----
    embed_k<<<dim3(2, LL/8, BB), 256>>>(SEAS, x_mark_dec, W_dec_tok, W_dec_tem,
                                        A_, S1H, S1L, X1F);
    run_attn(2, A_, S1H, S1L, S1H, S1L, X1F, dec_self_b,
             B_, V, QT, KT, SP, WW, DL, MH, ML, VH, VL, BVO4);
    decomp_k<<<dim3(2,8,BB), 256>>>(B_, A_, T123, DD, 1, S1H, S1L, X1F);
    run_attn(3, A_, S1H, S1L, ECH, ECL, ECF, dec_cross_b,
             B_, V, QT, KT, SP, WW, DL, MH, ML, VH, VL, BVO4);
    decomp_k<<<dim3(2,8,BB), 256>>>(B_, A_, T123, DD, 2, S1H, S1L, X1F);
    gemm2h(X1F, F1H + (size_t)2*DD*DFF, F1L + (size_t)2*DD*DFF,
           nullptr, nullptr, nullptr, X2F, DFF, DD, 1);
    gemm2h(X2F, F2H + (size_t)2*DFF*DD, F2L + (size_t)2*DFF*DD,
           nullptr, A_, B_, nullptr, DD, DFF, 0);
    decomp_k<<<dim3(2,8,BB), 256>>>(B_, A_, T123, DD, 2, S1H, S1L, X1F);
    trendconv_k<<<(BL7+255)/256, 256>>>(T123, dec_trend_W, TRD);
    ln_k<<<MROWS, 256>>>(A_, dec_ln_w, dec_ln_b, B_);
    zero_k<<<(BB*DD+255)/256, 256>>>(CM, BB*DD);
    colsum_k<<<dim3(2,8,BB), 256>>>(B_, CM);
    colsub_k<<<(BLD/4)/256, 256>>>(B_, CM, A_, nullptr, nullptr, nullptr);
    final_k<<<(BB*512*CIN+255)/256, 256>>>(A_, proj_W, proj_b, TRD, out);
}